// round 12
// baseline (speedup 1.0000x reference)
#include <cuda_runtime.h>
#include <cuda_fp16.h>
#include <math.h>
#include <stdint.h>

#define BB   2
#define SS   2048
#define DD   2048
#define HH   16
#define HD   128
#define DFF  8192
#define MROW 4096
#define QS   6144
#define EPSV 1e-5f

// ---------------- scratch ----------------
static __device__ __half g_xn  [(size_t)MROW*DD];
static __device__ __half g_qkv [(size_t)MROW*QS];
static __device__ __half g_ctx [(size_t)MROW*DD];
static __device__ __half g_h   [(size_t)MROW*DD];
static __device__ __half g_ff  [(size_t)MROW*DFF];
// fp16 weight copies, ORIGINAL K-major orientation (B frags via ldmatrix.trans)
static __device__ __half g_wqkv[(size_t)DD*QS];   // [2048][6144] packed Wq|Wk|Wv
static __device__ __half g_wo  [(size_t)DD*DD];
static __device__ __half g_w1  [(size_t)DD*DFF];
static __device__ __half g_w2  [(size_t)DFF*DD];

// ---------------- helpers ----------------
__device__ __forceinline__ uint32_t smem_u32(const void* p) {
    uint32_t a;
    asm("{ .reg .u64 t; cvta.to.shared.u64 t, %1; cvt.u32.u64 %0, t; }" : "=r"(a) : "l"(p));
    return a;
}
__device__ __forceinline__ void cp_async16(uint32_t s, const void* g) {
    asm volatile("cp.async.cg.shared.global [%0], [%1], 16;" :: "r"(s), "l"(g));
}
__device__ __forceinline__ void cp_commit() {
    asm volatile("cp.async.commit_group;" ::: "memory");
}
__device__ __forceinline__ void cp_wait1() {
    asm volatile("cp.async.wait_group 1;" ::: "memory");
}
__device__ __forceinline__ void cp_wait0() {
    asm volatile("cp.async.wait_group 0;" ::: "memory");
}
__device__ __forceinline__ void ldmx4(uint32_t* r, uint32_t addr) {
    asm volatile("ldmatrix.sync.aligned.m8n8.x4.shared.b16 {%0,%1,%2,%3}, [%4];"
        : "=r"(r[0]), "=r"(r[1]), "=r"(r[2]), "=r"(r[3]) : "r"(addr));
}
__device__ __forceinline__ void ldmx4t(uint32_t* r, uint32_t addr) {
    asm volatile("ldmatrix.sync.aligned.m8n8.x4.trans.shared.b16 {%0,%1,%2,%3}, [%4];"
        : "=r"(r[0]), "=r"(r[1]), "=r"(r[2]), "=r"(r[3]) : "r"(addr));
}
__device__ __forceinline__ void mma_f16(float* c, const uint32_t* a, const uint32_t* b) {
    asm volatile("mma.sync.aligned.m16n8k16.row.col.f32.f16.f16.f32 "
        "{%0,%1,%2,%3}, {%4,%5,%6,%7}, {%8,%9}, {%0,%1,%2,%3};"
        : "+f"(c[0]), "+f"(c[1]), "+f"(c[2]), "+f"(c[3])
        : "r"(a[0]), "r"(a[1]), "r"(a[2]), "r"(a[3]), "r"(b[0]), "r"(b[1]));
}
__device__ __forceinline__ uint32_t pack_h2(float a, float b) {
    __half2 t = __floats2half2_rn(a, b);
    return *reinterpret_cast<uint32_t*>(&t);
}
__device__ __forceinline__ float gelu_f(float x) {
    float x3 = x*x*x;
    return 0.5f * x * (1.0f + tanhf(0.79788456080286536f * (x + 0.044715f*x3)));
}

// ---------------- fp32 -> fp16 cast (optional column offset for QKV packing) ----------------
__global__ __launch_bounds__(256)
void cast_half(const float* __restrict__ src, __half* __restrict__ dst,
               int n8, int N, int colOff, int ldOut) {
    int i = blockIdx.x*256 + threadIdx.x;
    if (i >= n8) return;
    int cpr = N >> 3;
    int row = i / cpr, col8 = i - row*cpr;
    const float4* sp = (const float4*)(src + (size_t)row*N + col8*8);
    float4 a = sp[0], b = sp[1];
    __half h[8];
    h[0]=__float2half(a.x); h[1]=__float2half(a.y);
    h[2]=__float2half(a.z); h[3]=__float2half(a.w);
    h[4]=__float2half(b.x); h[5]=__float2half(b.y);
    h[6]=__float2half(b.z); h[7]=__float2half(b.w);
    *(uint4*)(dst + (size_t)row*ldOut + colOff + col8*8) = *(uint4*)h;
}

// ---------------- LayerNorm (T in -> fp16 out) ----------------
template<typename T>
__global__ __launch_bounds__(256)
void ln_kernel(const T* __restrict__ x, const float* __restrict__ sc,
               const float* __restrict__ sh, __half* __restrict__ out) {
    int row = blockIdx.x;
    const T* xr = x + (size_t)row * DD;
    float v[8];
    float s = 0.f, sq = 0.f;
#pragma unroll
    for (int i = 0; i < 8; i++) {
        v[i] = (float)xr[threadIdx.x + i*256];
        s += v[i]; sq += v[i]*v[i];
    }
    __shared__ float rs[8], rq[8];
    __shared__ float s_mean, s_rstd;
#pragma unroll
    for (int o = 16; o > 0; o >>= 1) {
        s  += __shfl_down_sync(0xFFFFFFFFu, s,  o);
        sq += __shfl_down_sync(0xFFFFFFFFu, sq, o);
    }
    int w = threadIdx.x >> 5;
    if ((threadIdx.x & 31) == 0) { rs[w] = s; rq[w] = sq; }
    __syncthreads();
    if (threadIdx.x == 0) {
        float ts = 0.f, tq = 0.f;
#pragma unroll
        for (int i = 0; i < 8; i++) { ts += rs[i]; tq += rq[i]; }
        float mean = ts * (1.0f/DD);
        s_mean = mean;
        s_rstd = rsqrtf(tq * (1.0f/DD) - mean*mean + EPSV);
    }
    __syncthreads();
    float mean = s_mean, rstd = s_rstd;
    __half* orow = out + (size_t)row * DD;
#pragma unroll
    for (int i = 0; i < 8; i++) {
        int d = threadIdx.x + i*256;
        orow[d] = __float2half(sc[d]*(v[i]-mean)*rstd + sh[d]);
    }
}

// ---------------- FP16 GEMM: C = A[M,K] @ W[K,N] (W K-major, trans B frags) ----------------
#define KSTEP   64
#define ROWH    72                        // A row: 64 + 8 pad halfs
#define BROWH   136                       // B row: 128 + 8 pad halfs
#define A_BYTES (128*ROWH*2)              // 18432
#define B_BYTES (KSTEP*BROWH*2)           // 17408
#define STG_B   (A_BYTES + B_BYTES)       // 35840
#define G_SMEM  (3*STG_B)                 // 107520

// EPI 0: Ch=acc
// EPI 1: Ch=half(acc+bias+Rf)
// EPI 2: Ch=half(gelu(acc+bias))
// EPI 3: Cf=acc+bias+Rh
template<int EPI>
__global__ __launch_bounds__(256, 2)
void mma_gemm(const __half* __restrict__ A, const __half* __restrict__ B,
              const float* __restrict__ bias, const float* __restrict__ Rf,
              const __half* __restrict__ Rh,
              float* __restrict__ Cf, __half* __restrict__ Ch, int N, int K) {
    extern __shared__ char dsm[];
    const int tid = threadIdx.x;
    const int lane = tid & 31;
    const int wid = tid >> 5;
    const int warpM = wid & 1;
    const int warpN = wid >> 1;
    const int m0 = blockIdx.y * 128;
    const int n0 = blockIdx.x * 128;
    const uint32_t sb = smem_u32(dsm);

    float acc[4][4][4];
#pragma unroll
    for (int i = 0; i < 4; i++)
#pragma unroll
        for (int j = 0; j < 4; j++)
#pragma unroll
            for (int u = 0; u < 4; u++) acc[i][j][u] = 0.f;

    const int NT = K / KSTEP;

    auto load_stage = [&](int s, int kk) {
        uint32_t ab = sb + s*STG_B;
        uint32_t bb = ab + A_BYTES;
#pragma unroll
        for (int i = 0; i < 4; i++) {
            int idx = i*256 + tid;
            int r = idx >> 3, c = idx & 7;       // A: 128 rows x 8 chunks
            cp_async16(ab + (r*ROWH + c*8)*2, A + (size_t)(m0 + r)*K + kk + c*8);
        }
#pragma unroll
        for (int i = 0; i < 4; i++) {
            int idx = i*256 + tid;
            int r = idx >> 4, c = idx & 15;      // B: 64 k-rows x 16 chunks of n
            cp_async16(bb + (r*BROWH + c*8)*2, B + (size_t)(kk + r)*N + n0 + c*8);
        }
    };

    load_stage(0, 0); cp_commit();
    load_stage(1, KSTEP); cp_commit();

    const int j  = lane >> 3;
    const int rr = lane & 7;
    const uint32_t offA  = ((warpM*64 + ((j&1)<<3) + rr) * ROWH + (j>>1)*8) * 2;
    const uint32_t offBt = (((j&1)*8 + rr) * BROWH + warpN*32 + (j>>1)*8) * 2;

    for (int t = 0; t < NT; t++) {
        cp_wait1();
        __syncthreads();
        if (t + 2 < NT) { load_stage((t+2)%3, (t+2)*KSTEP); cp_commit(); }

        int s = t % 3;
        uint32_t abase = sb + s*STG_B + offA;
        uint32_t bbase = sb + s*STG_B + A_BYTES + offBt;
#pragma unroll
        for (int k16 = 0; k16 < 4; k16++) {
            uint32_t ka  = abase + k16*32;
            uint32_t kbt = bbase + k16*(16*BROWH*2);
            uint32_t afr[4][4];
#pragma unroll
            for (int mt = 0; mt < 4; mt++)
                ldmx4(afr[mt], ka + mt*(16*ROWH*2));
            uint32_t b0[4], b1[4];
            ldmx4t(b0, kbt);           // n .. n+15
            ldmx4t(b1, kbt + 32);      // n+16 .. n+31
#pragma unroll
            for (int mt = 0; mt < 4; mt++) {
                mma_f16(acc[mt][0], afr[mt], b0);
                mma_f16(acc[mt][1], afr[mt], b0 + 2);
                mma_f16(acc[mt][2], afr[mt], b1);
                mma_f16(acc[mt][3], afr[mt], b1 + 2);
            }
        }
    }

#pragma unroll
    for (int mt = 0; mt < 4; mt++) {
#pragma unroll
        for (int half_ = 0; half_ < 2; half_++) {
            int m = m0 + warpM*64 + mt*16 + (lane >> 2) + half_*8;
#pragma unroll
            for (int nt = 0; nt < 4; nt++) {
                int n = n0 + warpN*32 + nt*8 + 2*(lane & 3);
                float v0 = acc[mt][nt][half_*2 + 0];
                float v1 = acc[mt][nt][half_*2 + 1];
                if (EPI == 0) {
                    *(__half2*)(Ch + (size_t)m*N + n) = __floats2half2_rn(v0, v1);
                } else if (EPI == 1) {
                    const float2 bb = *(const float2*)(bias + n);
                    const float2 rv = *(const float2*)(Rf + (size_t)m*N + n);
                    *(__half2*)(Ch + (size_t)m*N + n) =
                        __floats2half2_rn(v0 + bb.x + rv.x, v1 + bb.y + rv.y);
                } else if (EPI == 2) {
                    const float2 bb = *(const float2*)(bias + n);
                    *(__half2*)(Ch + (size_t)m*N + n) =
                        __floats2half2_rn(gelu_f(v0 + bb.x), gelu_f(v1 + bb.y));
                } else {
                    const float2 bb = *(const float2*)(bias + n);
                    __half2 rv = *(const __half2*)(Rh + (size_t)m*N + n);
                    float2 rf = __half22float2(rv);
                    float2 o; o.x = v0 + bb.x + rf.x; o.y = v1 + bb.y + rf.y;
                    *(float2*)(Cf + (size_t)m*N + n) = o;
                }
            }
        }
    }
}

// ---------------- causal flash attention (fp16, P-in-regs, cp.async KV ring) ----------------
#define KVROWH 136
#define KV_TILE (64*KVROWH*2)
#define KV_STG  (2*KV_TILE)
#define Q_BYTES (128*KVROWH*2)
#define ATT_SMEM (Q_BYTES + 2*KV_STG)

__global__ __launch_bounds__(256)
void attn_mma(const __half* __restrict__ Q, const __half* __restrict__ Kg,
              const __half* __restrict__ V, __half* __restrict__ O, int ld) {
    extern __shared__ __half hsm[];
    __half* Qs = hsm;
    const uint32_t sb = smem_u32(hsm);

    const int tid = threadIdx.x;
    const int lane = tid & 31;
    const int w = tid >> 5;
    const int r0 = lane >> 2;
    const int c0 = lane & 3;
    const int j  = lane >> 3;
    const int rr = lane & 7;
    const int q0 = blockIdx.x * 128;
    const int b = blockIdx.y >> 4;
    const int h = blockIdx.y & 15;
    const float rscale = 0.08838834764831845f;
    size_t ibase = ((size_t)b * SS) * ld + (size_t)h * HD;
    size_t obase = ((size_t)b * SS) * DD + (size_t)h * HD;

#pragma unroll
    for (int i = 0; i < 8; i++) {
        int idx = i*256 + tid;
        int r = idx >> 4, c = (idx & 15)*8;
        *(uint4*)(Qs + r*KVROWH + c) = *(const uint4*)(Q + ibase + (size_t)(q0 + r)*ld + c);
    }

    auto load_kv = [&](int kt) {
        int s = kt & 1;
        int k0 = kt * 64;
        uint32_t kb = sb + Q_BYTES + s*KV_STG;
        uint32_t vb = kb + KV_TILE;
#pragma unroll
        for (int i = 0; i < 4; i++) {
            int idx = i*256 + tid;
            int r = idx >> 4, c = (idx & 15)*8;
            cp_async16(kb + (r*KVROWH + c)*2, Kg + ibase + (size_t)(k0 + r)*ld + c);
            cp_async16(vb + (r*KVROWH + c)*2, V  + ibase + (size_t)(k0 + r)*ld + c);
        }
    };

    float acc[16][4];
#pragma unroll
    for (int i = 0; i < 16; i++)
#pragma unroll
        for (int u = 0; u < 4; u++) acc[i][u] = 0.f;
    float m0r = -1e30f, m1r = -1e30f, l0r = 0.f, l1r = 0.f;
    const int qi0 = q0 + w*16 + r0;
    const int qi1 = qi0 + 8;

    const uint32_t offQ = ((w*16 + ((j&1)<<3) + rr)*KVROWH + (j>>1)*8)*2;
    const uint32_t offK = (((j>>1)*8 + rr)*KVROWH + (j&1)*8)*2;
    const uint32_t offV = (((j&1)*8 + rr)*KVROWH + (j>>1)*8)*2;

    const int nkt = (q0 >> 6) + 2;
    load_kv(0); cp_commit();

    for (int kt = 0; kt < nkt; kt++) {
        int k0 = kt * 64;
        cp_wait0();
        __syncthreads();
        if (kt + 1 < nkt) { load_kv(kt + 1); cp_commit(); }

        int s = kt & 1;
        const uint32_t sK = sb + Q_BYTES + s*KV_STG;
        const uint32_t sV = sK + KV_TILE;

        float sc[8][4];
#pragma unroll
        for (int nt = 0; nt < 8; nt++)
#pragma unroll
            for (int u = 0; u < 4; u++) sc[nt][u] = 0.f;
#pragma unroll
        for (int kc = 0; kc < 8; kc++) {
            uint32_t a[4];
            ldmx4(a, sb + offQ + kc*32);
#pragma unroll
            for (int g = 0; g < 4; g++) {
                uint32_t bb[4];
                ldmx4(bb, sK + offK + kc*32 + g*(16*KVROWH*2));
                mma_f16(sc[2*g    ], a, bb);
                mma_f16(sc[2*g + 1], a, bb + 2);
            }
        }
#pragma unroll
        for (int nt = 0; nt < 8; nt++)
#pragma unroll
            for (int u = 0; u < 4; u++) sc[nt][u] *= rscale;
        if (k0 + 63 > qi0) {
#pragma unroll
            for (int nt = 0; nt < 8; nt++) {
                int cj = k0 + nt*8 + 2*c0;
                if (cj     > qi0) sc[nt][0] = -1e30f;
                if (cj + 1 > qi0) sc[nt][1] = -1e30f;
                if (cj     > qi1) sc[nt][2] = -1e30f;
                if (cj + 1 > qi1) sc[nt][3] = -1e30f;
            }
        }
        float tm0 = -1e30f, tm1 = -1e30f;
#pragma unroll
        for (int nt = 0; nt < 8; nt++) {
            tm0 = fmaxf(tm0, fmaxf(sc[nt][0], sc[nt][1]));
            tm1 = fmaxf(tm1, fmaxf(sc[nt][2], sc[nt][3]));
        }
        tm0 = fmaxf(tm0, __shfl_xor_sync(0xFFFFFFFFu, tm0, 1));
        tm0 = fmaxf(tm0, __shfl_xor_sync(0xFFFFFFFFu, tm0, 2));
        tm1 = fmaxf(tm1, __shfl_xor_sync(0xFFFFFFFFu, tm1, 1));
        tm1 = fmaxf(tm1, __shfl_xor_sync(0xFFFFFFFFu, tm1, 2));
        float mn0 = fmaxf(m0r, tm0), f0 = __expf(m0r - mn0);
        float mn1 = fmaxf(m1r, tm1), f1 = __expf(m1r - mn1);
        float ps0 = 0.f, ps1 = 0.f;
#pragma unroll
        for (int nt = 0; nt < 8; nt++) {
            sc[nt][0] = __expf(sc[nt][0] - mn0);
            sc[nt][1] = __expf(sc[nt][1] - mn0);
            sc[nt][2] = __expf(sc[nt][2] - mn1);
            sc[nt][3] = __expf(sc[nt][3] - mn1);
            ps0 += sc[nt][0] + sc[nt][1];
            ps1 += sc[nt][2] + sc[nt][3];
        }
        ps0 += __shfl_xor_sync(0xFFFFFFFFu, ps0, 1);
        ps0 += __shfl_xor_sync(0xFFFFFFFFu, ps0, 2);
        ps1 += __shfl_xor_sync(0xFFFFFFFFu, ps1, 1);
        ps1 += __shfl_xor_sync(0xFFFFFFFFu, ps1, 2);
        l0r = l0r*f0 + ps0; m0r = mn0;
        l1r = l1r*f1 + ps1; m1r = mn1;
#pragma unroll
        for (int nt = 0; nt < 16; nt++) {
            acc[nt][0] *= f0; acc[nt][1] *= f0;
            acc[nt][2] *= f1; acc[nt][3] *= f1;
        }
#pragma unroll
        for (int g = 0; g < 4; g++) {
            uint32_t a[4];
            a[0] = pack_h2(sc[2*g  ][0], sc[2*g  ][1]);
            a[1] = pack_h2(sc[2*g  ][2], sc[2*g  ][3]);
            a[2] = pack_h2(sc[2*g+1][0], sc[2*g+1][1]);
            a[3] = pack_h2(sc[2*g+1][2], sc[2*g+1][3]);
#pragma unroll
            for (int g2 = 0; g2 < 8; g2++) {
                uint32_t bb[4];
                ldmx4t(bb, sV + offV + g*(16*KVROWH*2) + g2*32);
                mma_f16(acc[2*g2    ], a, bb);
                mma_f16(acc[2*g2 + 1], a, bb + 2);
            }
        }
    }

    float inv0 = 1.0f / l0r, inv1 = 1.0f / l1r;
#pragma unroll
    for (int nt = 0; nt < 16; nt++) {
        int n = nt*8 + 2*c0;
        *(__half2*)(O + obase + (size_t)qi0*DD + n) = __floats2half2_rn(acc[nt][0]*inv0, acc[nt][1]*inv0);
        *(__half2*)(O + obase + (size_t)qi1*DD + n) = __floats2half2_rn(acc[nt][2]*inv1, acc[nt][3]*inv1);
    }
}

// ---------------- launch ----------------
extern "C" void kernel_launch(void* const* d_in, const int* in_sizes, int n_in,
                              void* d_out, int out_size) {
    const float* x    = (const float*)d_in[0];
    const float* Wq   = (const float*)d_in[1];
    const float* Wk   = (const float*)d_in[2];
    const float* Wv   = (const float*)d_in[3];
    const float* Wo   = (const float*)d_in[4];
    const float* bo   = (const float*)d_in[5];
    const float* ln1s = (const float*)d_in[6];
    const float* ln1b = (const float*)d_in[7];
    const float* ln2s = (const float*)d_in[8];
    const float* ln2b = (const float*)d_in[9];
    const float* W1   = (const float*)d_in[10];
    const float* b1   = (const float*)d_in[11];
    const float* W2   = (const float*)d_in[12];
    const float* b2   = (const float*)d_in[13];
    float* out = (float*)d_out;

    __half *xn, *qkv, *ctx, *h, *ff, *wqkv, *wo, *w1, *w2;
    cudaGetSymbolAddress((void**)&xn,   g_xn);
    cudaGetSymbolAddress((void**)&qkv,  g_qkv);
    cudaGetSymbolAddress((void**)&ctx,  g_ctx);
    cudaGetSymbolAddress((void**)&h,    g_h);
    cudaGetSymbolAddress((void**)&ff,   g_ff);
    cudaGetSymbolAddress((void**)&wqkv, g_wqkv);
    cudaGetSymbolAddress((void**)&wo,   g_wo);
    cudaGetSymbolAddress((void**)&w1,   g_w1);
    cudaGetSymbolAddress((void**)&w2,   g_w2);

    cudaFuncSetAttribute(attn_mma, cudaFuncAttributeMaxDynamicSharedMemorySize, ATT_SMEM);
    cudaFuncSetAttribute(mma_gemm<0>, cudaFuncAttributeMaxDynamicSharedMemorySize, G_SMEM);
    cudaFuncSetAttribute(mma_gemm<1>, cudaFuncAttributeMaxDynamicSharedMemorySize, G_SMEM);
    cudaFuncSetAttribute(mma_gemm<2>, cudaFuncAttributeMaxDynamicSharedMemorySize, G_SMEM);
    cudaFuncSetAttribute(mma_gemm<3>, cudaFuncAttributeMaxDynamicSharedMemorySize, G_SMEM);

    // fp32 -> fp16 weight casts (no transpose; B frags use ldmatrix.trans)
    const int c4 = DD*DD/8, c16 = DD*DFF/8;
    cast_half<<<(c4 +255)/256, 256>>>(Wq, wqkv, c4,  DD,  0,    QS);
    cast_half<<<(c4 +255)/256, 256>>>(Wk, wqkv, c4,  DD,  2048, QS);
    cast_half<<<(c4 +255)/256, 256>>>(Wv, wqkv, c4,  DD,  4096, QS);
    cast_half<<<(c4 +255)/256, 256>>>(Wo, wo,   c4,  DD,  0,    DD);
    cast_half<<<(c16+255)/256, 256>>>(W1, w1,   c16, DFF, 0,    DFF);
    cast_half<<<(c16+255)/256, 256>>>(W2, w2,   c16, DD,  0,    DD);

    ln_kernel<float><<<MROW, 256>>>(x, ln1s, ln1b, xn);
    mma_gemm<0><<<dim3(QS/128, MROW/128), 256, G_SMEM>>>(
        xn, wqkv, nullptr, nullptr, nullptr, nullptr, qkv, QS, DD);
    attn_mma<<<dim3(SS/128, BB*HH), 256, ATT_SMEM>>>(qkv, qkv + 2048, qkv + 4096, ctx, QS);
    mma_gemm<1><<<dim3(DD/128, MROW/128), 256, G_SMEM>>>(
        ctx, wo, bo, x, nullptr, nullptr, h, DD, DD);
    ln_kernel<__half><<<MROW, 256>>>(h, ln2s, ln2b, xn);
    mma_gemm<2><<<dim3(DFF/128, MROW/128), 256, G_SMEM>>>(
        xn, w1, b1, nullptr, nullptr, nullptr, ff, DFF, DD);
    mma_gemm<3><<<dim3(DD/128, MROW/128), 256, G_SMEM>>>(
        ff, w2, b2, nullptr, h, out, nullptr, DD, DFF);
}

// round 13
// speedup vs baseline: 1.0152x; 1.0152x over previous
#include <cuda_runtime.h>
#include <cuda_fp16.h>
#include <math.h>
#include <stdint.h>

#define BB   2
#define SS   2048
#define DD   2048
#define HH   16
#define HD   128
#define DFF  8192
#define MROW 4096
#define QS   6144
#define EPSV 1e-5f

// ---------------- scratch ----------------
static __device__ __half g_xn  [(size_t)MROW*DD];
static __device__ __half g_qkv [(size_t)MROW*QS];
static __device__ __half g_ctx [(size_t)MROW*DD];
static __device__ __half g_h   [(size_t)MROW*DD];
static __device__ __half g_ff  [(size_t)MROW*DFF];
// transposed fp16 weights Wt[N][K]  (R10 proven-best GEMM layout)
static __device__ __half g_wqkvT[(size_t)QS*DD];
static __device__ __half g_woT  [(size_t)DD*DD];
static __device__ __half g_w1T  [(size_t)DFF*DD];
static __device__ __half g_w2T  [(size_t)DD*DFF];

// ---------------- helpers ----------------
__device__ __forceinline__ uint32_t smem_u32(const void* p) {
    uint32_t a;
    asm("{ .reg .u64 t; cvta.to.shared.u64 t, %1; cvt.u32.u64 %0, t; }" : "=r"(a) : "l"(p));
    return a;
}
__device__ __forceinline__ void cp_async16(uint32_t s, const void* g) {
    asm volatile("cp.async.cg.shared.global [%0], [%1], 16;" :: "r"(s), "l"(g));
}
__device__ __forceinline__ void cp_commit() {
    asm volatile("cp.async.commit_group;" ::: "memory");
}
__device__ __forceinline__ void cp_wait1() {
    asm volatile("cp.async.wait_group 1;" ::: "memory");
}
__device__ __forceinline__ void cp_wait0() {
    asm volatile("cp.async.wait_group 0;" ::: "memory");
}
__device__ __forceinline__ void ldmx4(uint32_t* r, uint32_t addr) {
    asm volatile("ldmatrix.sync.aligned.m8n8.x4.shared.b16 {%0,%1,%2,%3}, [%4];"
        : "=r"(r[0]), "=r"(r[1]), "=r"(r[2]), "=r"(r[3]) : "r"(addr));
}
__device__ __forceinline__ void ldmx4t(uint32_t* r, uint32_t addr) {
    asm volatile("ldmatrix.sync.aligned.m8n8.x4.trans.shared.b16 {%0,%1,%2,%3}, [%4];"
        : "=r"(r[0]), "=r"(r[1]), "=r"(r[2]), "=r"(r[3]) : "r"(addr));
}
__device__ __forceinline__ void mma_f16(float* c, const uint32_t* a, const uint32_t* b) {
    asm volatile("mma.sync.aligned.m16n8k16.row.col.f32.f16.f16.f32 "
        "{%0,%1,%2,%3}, {%4,%5,%6,%7}, {%8,%9}, {%0,%1,%2,%3};"
        : "+f"(c[0]), "+f"(c[1]), "+f"(c[2]), "+f"(c[3])
        : "r"(a[0]), "r"(a[1]), "r"(a[2]), "r"(a[3]), "r"(b[0]), "r"(b[1]));
}
__device__ __forceinline__ uint32_t pack_h2(float a, float b) {
    __half2 t = __floats2half2_rn(a, b);
    return *reinterpret_cast<uint32_t*>(&t);
}
__device__ __forceinline__ float gelu_f(float x) {
    float x3 = x*x*x;
    return 0.5f * x * (1.0f + tanhf(0.79788456080286536f * (x + 0.044715f*x3)));
}

// ---------------- weight transpose -> fp16 ----------------
__global__ __launch_bounds__(256)
void transpose_half(const float* __restrict__ W, __half* __restrict__ Wt,
                    int K, int N, int rowOff, int ldOut) {
    __shared__ float t[32][33];
    int k0 = blockIdx.y * 32, n0 = blockIdx.x * 32;
    int tx = threadIdx.x, ty = threadIdx.y;
#pragma unroll
    for (int i = 0; i < 4; i++)
        t[ty*4+i][tx] = W[(size_t)(k0 + ty*4 + i) * N + n0 + tx];
    __syncthreads();
#pragma unroll
    for (int i = 0; i < 4; i++)
        Wt[(size_t)(rowOff + n0 + ty*4 + i) * ldOut + k0 + tx] = __float2half(t[tx][ty*4+i]);
}

// ---------------- LayerNorm (T in -> fp16 out) ----------------
template<typename T>
__global__ __launch_bounds__(256)
void ln_kernel(const T* __restrict__ x, const float* __restrict__ sc,
               const float* __restrict__ sh, __half* __restrict__ out) {
    int row = blockIdx.x;
    const T* xr = x + (size_t)row * DD;
    float v[8];
    float s = 0.f, sq = 0.f;
#pragma unroll
    for (int i = 0; i < 8; i++) {
        v[i] = (float)xr[threadIdx.x + i*256];
        s += v[i]; sq += v[i]*v[i];
    }
    __shared__ float rs[8], rq[8];
    __shared__ float s_mean, s_rstd;
#pragma unroll
    for (int o = 16; o > 0; o >>= 1) {
        s  += __shfl_down_sync(0xFFFFFFFFu, s,  o);
        sq += __shfl_down_sync(0xFFFFFFFFu, sq, o);
    }
    int w = threadIdx.x >> 5;
    if ((threadIdx.x & 31) == 0) { rs[w] = s; rq[w] = sq; }
    __syncthreads();
    if (threadIdx.x == 0) {
        float ts = 0.f, tq = 0.f;
#pragma unroll
        for (int i = 0; i < 8; i++) { ts += rs[i]; tq += rq[i]; }
        float mean = ts * (1.0f/DD);
        s_mean = mean;
        s_rstd = rsqrtf(tq * (1.0f/DD) - mean*mean + EPSV);
    }
    __syncthreads();
    float mean = s_mean, rstd = s_rstd;
    __half* orow = out + (size_t)row * DD;
#pragma unroll
    for (int i = 0; i < 8; i++) {
        int d = threadIdx.x + i*256;
        orow[d] = __float2half(sc[d]*(v[i]-mean)*rstd + sh[d]);
    }
}

// ---------------- FP16 GEMM: C = A[M,K] @ Wt[N,K]^T (R10 layout) ----------------
#define KSTEP   64
#define ROWH    72
#define T_BYTES (128*ROWH*2)
#define STG_B   (2*T_BYTES)
#define G_SMEM  (3*STG_B)

// EPI 0: Ch=acc
// EPI 1: Ch=half(acc+bias+Rf)    (fp32 residual in, half out)
// EPI 2: Ch=half(gelu(acc+bias))
// EPI 3: Cf=acc+bias+Rh          (half residual in, fp32 out)
template<int EPI>
__global__ __launch_bounds__(256, 2)
void mma_gemm(const __half* __restrict__ A, const __half* __restrict__ Bt,
              const float* __restrict__ bias, const float* __restrict__ Rf,
              const __half* __restrict__ Rh,
              float* __restrict__ Cf, __half* __restrict__ Ch, int N, int K) {
    extern __shared__ char dsm[];
    const int tid = threadIdx.x;
    const int lane = tid & 31;
    const int wid = tid >> 5;
    const int warpM = wid & 1;
    const int warpN = wid >> 1;
    const int m0 = blockIdx.y * 128;
    const int n0 = blockIdx.x * 128;
    const uint32_t sb = smem_u32(dsm);

    float acc[4][4][4];
#pragma unroll
    for (int i = 0; i < 4; i++)
#pragma unroll
        for (int j = 0; j < 4; j++)
#pragma unroll
            for (int u = 0; u < 4; u++) acc[i][j][u] = 0.f;

    const int NT = K / KSTEP;

    auto load_stage = [&](int s, int kk) {
        uint32_t ab = sb + s*STG_B;
        uint32_t bb = ab + T_BYTES;
#pragma unroll
        for (int i = 0; i < 4; i++) {
            int idx = i*256 + tid;
            int r = idx >> 3, c = idx & 7;
            cp_async16(ab + (r*ROWH + c*8)*2, A  + (size_t)(m0 + r)*K + kk + c*8);
            cp_async16(bb + (r*ROWH + c*8)*2, Bt + (size_t)(n0 + r)*K + kk + c*8);
        }
    };

    load_stage(0, 0); cp_commit();
    load_stage(1, KSTEP); cp_commit();

    const int j  = lane >> 3;
    const int rr = lane & 7;
    const uint32_t offA = ((warpM*64 + ((j&1)<<3) + rr) * ROWH + (j>>1)*8) * 2;
    const uint32_t offB = ((warpN*32 + (j>>1)*8  + rr) * ROWH + (j&1)*8) * 2;

    for (int t = 0; t < NT; t++) {
        cp_wait1();
        __syncthreads();
        if (t + 2 < NT) { load_stage((t+2)%3, (t+2)*KSTEP); cp_commit(); }

        int s = t % 3;
        uint32_t abase = sb + s*STG_B + offA;
        uint32_t bbase = sb + s*STG_B + T_BYTES + offB;
#pragma unroll
        for (int k16 = 0; k16 < 4; k16++) {
            uint32_t ka = abase + k16*32;
            uint32_t kb = bbase + k16*32;
            uint32_t afr[4][4];
#pragma unroll
            for (int mt = 0; mt < 4; mt++)
                ldmx4(afr[mt], ka + mt*(16*ROWH*2));
            uint32_t bfr[4][2];
            ldmx4(&bfr[0][0], kb);
            ldmx4(&bfr[2][0], kb + 16*ROWH*2);
#pragma unroll
            for (int mt = 0; mt < 4; mt++)
#pragma unroll
                for (int nt = 0; nt < 4; nt++)
                    mma_f16(acc[mt][nt], afr[mt], bfr[nt]);
        }
    }

#pragma unroll
    for (int mt = 0; mt < 4; mt++) {
#pragma unroll
        for (int half_ = 0; half_ < 2; half_++) {
            int m = m0 + warpM*64 + mt*16 + (lane >> 2) + half_*8;
#pragma unroll
            for (int nt = 0; nt < 4; nt++) {
                int n = n0 + warpN*32 + nt*8 + 2*(lane & 3);
                float v0 = acc[mt][nt][half_*2 + 0];
                float v1 = acc[mt][nt][half_*2 + 1];
                if (EPI == 0) {
                    *(__half2*)(Ch + (size_t)m*N + n) = __floats2half2_rn(v0, v1);
                } else if (EPI == 1) {
                    const float2 bb = *(const float2*)(bias + n);
                    const float2 rv = *(const float2*)(Rf + (size_t)m*N + n);
                    *(__half2*)(Ch + (size_t)m*N + n) =
                        __floats2half2_rn(v0 + bb.x + rv.x, v1 + bb.y + rv.y);
                } else if (EPI == 2) {
                    const float2 bb = *(const float2*)(bias + n);
                    *(__half2*)(Ch + (size_t)m*N + n) =
                        __floats2half2_rn(gelu_f(v0 + bb.x), gelu_f(v1 + bb.y));
                } else {
                    const float2 bb = *(const float2*)(bias + n);
                    __half2 rv = *(const __half2*)(Rh + (size_t)m*N + n);
                    float2 rf = __half22float2(rv);
                    float2 o; o.x = v0 + bb.x + rf.x; o.y = v1 + bb.y + rf.y;
                    *(float2*)(Cf + (size_t)m*N + n) = o;
                }
            }
        }
    }
}

// ---------------- causal flash attention (fp16, P-in-regs, cp.async KV ring, 2 CTA/SM) ----------------
#define KVROWH 136
#define KV_TILE (64*KVROWH*2)
#define KV_STG  (2*KV_TILE)
#define Q_BYTES (128*KVROWH*2)
#define ATT_SMEM (Q_BYTES + 2*KV_STG)

__global__ __launch_bounds__(256, 2)
void attn_mma(const __half* __restrict__ Q, const __half* __restrict__ Kg,
              const __half* __restrict__ V, __half* __restrict__ O, int ld) {
    extern __shared__ __half hsm[];
    __half* Qs = hsm;
    const uint32_t sb = smem_u32(hsm);

    const int tid = threadIdx.x;
    const int lane = tid & 31;
    const int w = tid >> 5;
    const int r0 = lane >> 2;
    const int c0 = lane & 3;
    const int j  = lane >> 3;
    const int rr = lane & 7;
    const int q0 = blockIdx.x * 128;
    const int b = blockIdx.y >> 4;
    const int h = blockIdx.y & 15;
    const float rscale = 0.08838834764831845f;
    size_t ibase = ((size_t)b * SS) * ld + (size_t)h * HD;
    size_t obase = ((size_t)b * SS) * DD + (size_t)h * HD;

#pragma unroll
    for (int i = 0; i < 8; i++) {
        int idx = i*256 + tid;
        int r = idx >> 4, c = (idx & 15)*8;
        *(uint4*)(Qs + r*KVROWH + c) = *(const uint4*)(Q + ibase + (size_t)(q0 + r)*ld + c);
    }

    auto load_kv = [&](int kt) {
        int s = kt & 1;
        int k0 = kt * 64;
        uint32_t kb = sb + Q_BYTES + s*KV_STG;
        uint32_t vb = kb + KV_TILE;
#pragma unroll
        for (int i = 0; i < 4; i++) {
            int idx = i*256 + tid;
            int r = idx >> 4, c = (idx & 15)*8;
            cp_async16(kb + (r*KVROWH + c)*2, Kg + ibase + (size_t)(k0 + r)*ld + c);
            cp_async16(vb + (r*KVROWH + c)*2, V  + ibase + (size_t)(k0 + r)*ld + c);
        }
    };

    float acc[16][4];
#pragma unroll
    for (int i = 0; i < 16; i++)
#pragma unroll
        for (int u = 0; u < 4; u++) acc[i][u] = 0.f;
    float m0r = -1e30f, m1r = -1e30f, l0r = 0.f, l1r = 0.f;
    const int qi0 = q0 + w*16 + r0;
    const int qi1 = qi0 + 8;

    const uint32_t offQ = ((w*16 + ((j&1)<<3) + rr)*KVROWH + (j>>1)*8)*2;
    const uint32_t offK = (((j>>1)*8 + rr)*KVROWH + (j&1)*8)*2;
    const uint32_t offV = (((j&1)*8 + rr)*KVROWH + (j>>1)*8)*2;

    const int nkt = (q0 >> 6) + 2;
    load_kv(0); cp_commit();

    for (int kt = 0; kt < nkt; kt++) {
        int k0 = kt * 64;
        cp_wait0();
        __syncthreads();
        if (kt + 1 < nkt) { load_kv(kt + 1); cp_commit(); }

        int s = kt & 1;
        const uint32_t sK = sb + Q_BYTES + s*KV_STG;
        const uint32_t sV = sK + KV_TILE;

        float sc[8][4];
#pragma unroll
        for (int nt = 0; nt < 8; nt++)
#pragma unroll
            for (int u = 0; u < 4; u++) sc[nt][u] = 0.f;
#pragma unroll
        for (int kc = 0; kc < 8; kc++) {
            uint32_t a[4];
            ldmx4(a, sb + offQ + kc*32);
#pragma unroll
            for (int g = 0; g < 4; g++) {
                uint32_t bb[4];
                ldmx4(bb, sK + offK + kc*32 + g*(16*KVROWH*2));
                mma_f16(sc[2*g    ], a, bb);
                mma_f16(sc[2*g + 1], a, bb + 2);
            }
        }
#pragma unroll
        for (int nt = 0; nt < 8; nt++)
#pragma unroll
            for (int u = 0; u < 4; u++) sc[nt][u] *= rscale;
        if (k0 + 63 > qi0) {
#pragma unroll
            for (int nt = 0; nt < 8; nt++) {
                int cj = k0 + nt*8 + 2*c0;
                if (cj     > qi0) sc[nt][0] = -1e30f;
                if (cj + 1 > qi0) sc[nt][1] = -1e30f;
                if (cj     > qi1) sc[nt][2] = -1e30f;
                if (cj + 1 > qi1) sc[nt][3] = -1e30f;
            }
        }
        float tm0 = -1e30f, tm1 = -1e30f;
#pragma unroll
        for (int nt = 0; nt < 8; nt++) {
            tm0 = fmaxf(tm0, fmaxf(sc[nt][0], sc[nt][1]));
            tm1 = fmaxf(tm1, fmaxf(sc[nt][2], sc[nt][3]));
        }
        tm0 = fmaxf(tm0, __shfl_xor_sync(0xFFFFFFFFu, tm0, 1));
        tm0 = fmaxf(tm0, __shfl_xor_sync(0xFFFFFFFFu, tm0, 2));
        tm1 = fmaxf(tm1, __shfl_xor_sync(0xFFFFFFFFu, tm1, 1));
        tm1 = fmaxf(tm1, __shfl_xor_sync(0xFFFFFFFFu, tm1, 2));
        float mn0 = fmaxf(m0r, tm0), f0 = __expf(m0r - mn0);
        float mn1 = fmaxf(m1r, tm1), f1 = __expf(m1r - mn1);
        float ps0 = 0.f, ps1 = 0.f;
#pragma unroll
        for (int nt = 0; nt < 8; nt++) {
            sc[nt][0] = __expf(sc[nt][0] - mn0);
            sc[nt][1] = __expf(sc[nt][1] - mn0);
            sc[nt][2] = __expf(sc[nt][2] - mn1);
            sc[nt][3] = __expf(sc[nt][3] - mn1);
            ps0 += sc[nt][0] + sc[nt][1];
            ps1 += sc[nt][2] + sc[nt][3];
        }
        ps0 += __shfl_xor_sync(0xFFFFFFFFu, ps0, 1);
        ps0 += __shfl_xor_sync(0xFFFFFFFFu, ps0, 2);
        ps1 += __shfl_xor_sync(0xFFFFFFFFu, ps1, 1);
        ps1 += __shfl_xor_sync(0xFFFFFFFFu, ps1, 2);
        l0r = l0r*f0 + ps0; m0r = mn0;
        l1r = l1r*f1 + ps1; m1r = mn1;
#pragma unroll
        for (int nt = 0; nt < 16; nt++) {
            acc[nt][0] *= f0; acc[nt][1] *= f0;
            acc[nt][2] *= f1; acc[nt][3] *= f1;
        }
#pragma unroll
        for (int g = 0; g < 4; g++) {
            uint32_t a[4];
            a[0] = pack_h2(sc[2*g  ][0], sc[2*g  ][1]);
            a[1] = pack_h2(sc[2*g  ][2], sc[2*g  ][3]);
            a[2] = pack_h2(sc[2*g+1][0], sc[2*g+1][1]);
            a[3] = pack_h2(sc[2*g+1][2], sc[2*g+1][3]);
#pragma unroll
            for (int g2 = 0; g2 < 8; g2++) {
                uint32_t bb[4];
                ldmx4t(bb, sV + offV + g*(16*KVROWH*2) + g2*32);
                mma_f16(acc[2*g2    ], a, bb);
                mma_f16(acc[2*g2 + 1], a, bb + 2);
            }
        }
    }

    float inv0 = 1.0f / l0r, inv1 = 1.0f / l1r;
#pragma unroll
    for (int nt = 0; nt < 16; nt++) {
        int n = nt*8 + 2*c0;
        *(__half2*)(O + obase + (size_t)qi0*DD + n) = __floats2half2_rn(acc[nt][0]*inv0, acc[nt][1]*inv0);
        *(__half2*)(O + obase + (size_t)qi1*DD + n) = __floats2half2_rn(acc[nt][2]*inv1, acc[nt][3]*inv1);
    }
}

// ---------------- launch ----------------
extern "C" void kernel_launch(void* const* d_in, const int* in_sizes, int n_in,
                              void* d_out, int out_size) {
    const float* x    = (const float*)d_in[0];
    const float* Wq   = (const float*)d_in[1];
    const float* Wk   = (const float*)d_in[2];
    const float* Wv   = (const float*)d_in[3];
    const float* Wo   = (const float*)d_in[4];
    const float* bo   = (const float*)d_in[5];
    const float* ln1s = (const float*)d_in[6];
    const float* ln1b = (const float*)d_in[7];
    const float* ln2s = (const float*)d_in[8];
    const float* ln2b = (const float*)d_in[9];
    const float* W1   = (const float*)d_in[10];
    const float* b1   = (const float*)d_in[11];
    const float* W2   = (const float*)d_in[12];
    const float* b2   = (const float*)d_in[13];
    float* out = (float*)d_out;

    __half *xn, *qkv, *ctx, *h, *ff, *wqkvT, *woT, *w1T, *w2T;
    cudaGetSymbolAddress((void**)&xn,    g_xn);
    cudaGetSymbolAddress((void**)&qkv,   g_qkv);
    cudaGetSymbolAddress((void**)&ctx,   g_ctx);
    cudaGetSymbolAddress((void**)&h,     g_h);
    cudaGetSymbolAddress((void**)&ff,    g_ff);
    cudaGetSymbolAddress((void**)&wqkvT, g_wqkvT);
    cudaGetSymbolAddress((void**)&woT,   g_woT);
    cudaGetSymbolAddress((void**)&w1T,   g_w1T);
    cudaGetSymbolAddress((void**)&w2T,   g_w2T);

    cudaFuncSetAttribute(attn_mma, cudaFuncAttributeMaxDynamicSharedMemorySize, ATT_SMEM);
    cudaFuncSetAttribute(mma_gemm<0>, cudaFuncAttributeMaxDynamicSharedMemorySize, G_SMEM);
    cudaFuncSetAttribute(mma_gemm<1>, cudaFuncAttributeMaxDynamicSharedMemorySize, G_SMEM);
    cudaFuncSetAttribute(mma_gemm<2>, cudaFuncAttributeMaxDynamicSharedMemorySize, G_SMEM);
    cudaFuncSetAttribute(mma_gemm<3>, cudaFuncAttributeMaxDynamicSharedMemorySize, G_SMEM);

    dim3 t32(32, 8);
    transpose_half<<<dim3(DD/32,  DD/32), t32>>>(Wq, wqkvT, DD, DD, 0,    DD);
    transpose_half<<<dim3(DD/32,  DD/32), t32>>>(Wk, wqkvT, DD, DD, 2048, DD);
    transpose_half<<<dim3(DD/32,  DD/32), t32>>>(Wv, wqkvT, DD, DD, 4096, DD);
    transpose_half<<<dim3(DD/32,  DD/32), t32>>>(Wo, woT, DD, DD, 0, DD);
    transpose_half<<<dim3(DFF/32, DD/32), t32>>>(W1, w1T, DD, DFF, 0, DD);
    transpose_half<<<dim3(DD/32, DFF/32), t32>>>(W2, w2T, DFF, DD, 0, DFF);

    ln_kernel<float><<<MROW, 256>>>(x, ln1s, ln1b, xn);
    mma_gemm<0><<<dim3(QS/128, MROW/128), 256, G_SMEM>>>(
        xn, wqkvT, nullptr, nullptr, nullptr, nullptr, qkv, QS, DD);
    attn_mma<<<dim3(SS/128, BB*HH), 256, ATT_SMEM>>>(qkv, qkv + 2048, qkv + 4096, ctx, QS);
    // Wo proj: fp32 residual x in, half h out
    mma_gemm<1><<<dim3(DD/128, MROW/128), 256, G_SMEM>>>(
        ctx, woT, bo, x, nullptr, nullptr, h, DD, DD);
    ln_kernel<__half><<<MROW, 256>>>(h, ln2s, ln2b, xn);
    mma_gemm<2><<<dim3(DFF/128, MROW/128), 256, G_SMEM>>>(
        xn, w1T, b1, nullptr, nullptr, nullptr, ff, DFF, DD);
    // FFN down: half residual h in, fp32 out
    mma_gemm<3><<<dim3(DD/128, MROW/128), 256, G_SMEM>>>(
        ff, w2T, b2, nullptr, h, out, nullptr, DD, DFF);
}

// round 14
// speedup vs baseline: 1.0348x; 1.0193x over previous
#include <cuda_runtime.h>
#include <cuda_fp16.h>
#include <math.h>
#include <stdint.h>

#define BB   2
#define SS   2048
#define DD   2048
#define HH   16
#define HD   128
#define DFF  8192
#define MROW 4096
#define QS   6144
#define EPSV 1e-5f

// ---------------- scratch ----------------
static __device__ __half g_xn  [(size_t)MROW*DD];
static __device__ __half g_qkv [(size_t)MROW*QS];
static __device__ __half g_ctx [(size_t)MROW*DD];
static __device__ __half g_h   [(size_t)MROW*DD];
static __device__ __half g_ff  [(size_t)MROW*DFF];
static __device__ __half g_wqkvT[(size_t)QS*DD];
static __device__ __half g_woT  [(size_t)DD*DD];
static __device__ __half g_w1T  [(size_t)DFF*DD];
static __device__ __half g_w2T  [(size_t)DD*DFF];

// ---------------- helpers ----------------
__device__ __forceinline__ uint32_t smem_u32(const void* p) {
    uint32_t a;
    asm("{ .reg .u64 t; cvta.to.shared.u64 t, %1; cvt.u32.u64 %0, t; }" : "=r"(a) : "l"(p));
    return a;
}
__device__ __forceinline__ void cp_async16(uint32_t s, const void* g) {
    asm volatile("cp.async.cg.shared.global [%0], [%1], 16;" :: "r"(s), "l"(g));
}
__device__ __forceinline__ void cp_commit() {
    asm volatile("cp.async.commit_group;" ::: "memory");
}
__device__ __forceinline__ void cp_wait1() {
    asm volatile("cp.async.wait_group 1;" ::: "memory");
}
__device__ __forceinline__ void cp_wait0() {
    asm volatile("cp.async.wait_group 0;" ::: "memory");
}
__device__ __forceinline__ void ldmx4(uint32_t* r, uint32_t addr) {
    asm volatile("ldmatrix.sync.aligned.m8n8.x4.shared.b16 {%0,%1,%2,%3}, [%4];"
        : "=r"(r[0]), "=r"(r[1]), "=r"(r[2]), "=r"(r[3]) : "r"(addr));
}
__device__ __forceinline__ void ldmx4t(uint32_t* r, uint32_t addr) {
    asm volatile("ldmatrix.sync.aligned.m8n8.x4.trans.shared.b16 {%0,%1,%2,%3}, [%4];"
        : "=r"(r[0]), "=r"(r[1]), "=r"(r[2]), "=r"(r[3]) : "r"(addr));
}
__device__ __forceinline__ void mma_f16(float* c, const uint32_t* a, const uint32_t* b) {
    asm volatile("mma.sync.aligned.m16n8k16.row.col.f32.f16.f16.f32 "
        "{%0,%1,%2,%3}, {%4,%5,%6,%7}, {%8,%9}, {%0,%1,%2,%3};"
        : "+f"(c[0]), "+f"(c[1]), "+f"(c[2]), "+f"(c[3])
        : "r"(a[0]), "r"(a[1]), "r"(a[2]), "r"(a[3]), "r"(b[0]), "r"(b[1]));
}
__device__ __forceinline__ uint32_t pack_h2(float a, float b) {
    __half2 t = __floats2half2_rn(a, b);
    return *reinterpret_cast<uint32_t*>(&t);
}
__device__ __forceinline__ float gelu_f(float x) {
    float x3 = x*x*x;
    return 0.5f * x * (1.0f + tanhf(0.79788456080286536f * (x + 0.044715f*x3)));
}

// ---------------- weight transpose -> fp16 (64x64 tiles, 16B coalesced writes) ----------------
__global__ __launch_bounds__(256)
void transpose_half(const float* __restrict__ W, __half* __restrict__ Wt,
                    int K, int N, int rowOff, int ldOut) {
    __shared__ float t[64][65];
    int k0 = blockIdx.y * 64, n0 = blockIdx.x * 64;
    int tx = threadIdx.x;
#pragma unroll
    for (int i = 0; i < 4; i++) {
        int idx = i*256 + tx;               // 0..1023 float4 chunks
        int r = idx >> 4, c4 = (idx & 15)*4;
        float4 v = *(const float4*)(W + (size_t)(k0 + r)*N + n0 + c4);
        t[r][c4] = v.x; t[r][c4+1] = v.y; t[r][c4+2] = v.z; t[r][c4+3] = v.w;
    }
    __syncthreads();
#pragma unroll
    for (int i = 0; i < 2; i++) {
        int idx = i*256 + tx;               // 0..511 uint4 chunks
        int r = idx >> 3, c8 = (idx & 7)*8; // r = n-row, c8 = k-col
        __half h[8];
#pragma unroll
        for (int u = 0; u < 8; u++) h[u] = __float2half(t[c8 + u][r]);
        *(uint4*)(Wt + (size_t)(rowOff + n0 + r)*ldOut + k0 + c8) = *(uint4*)h;
    }
}

// ---------------- LayerNorm (T in -> fp16 out) ----------------
template<typename T>
__global__ __launch_bounds__(256)
void ln_kernel(const T* __restrict__ x, const float* __restrict__ sc,
               const float* __restrict__ sh, __half* __restrict__ out) {
    int row = blockIdx.x;
    const T* xr = x + (size_t)row * DD;
    float v[8];
    float s = 0.f, sq = 0.f;
#pragma unroll
    for (int i = 0; i < 8; i++) {
        v[i] = (float)xr[threadIdx.x + i*256];
        s += v[i]; sq += v[i]*v[i];
    }
    __shared__ float rs[8], rq[8];
    __shared__ float s_mean, s_rstd;
#pragma unroll
    for (int o = 16; o > 0; o >>= 1) {
        s  += __shfl_down_sync(0xFFFFFFFFu, s,  o);
        sq += __shfl_down_sync(0xFFFFFFFFu, sq, o);
    }
    int w = threadIdx.x >> 5;
    if ((threadIdx.x & 31) == 0) { rs[w] = s; rq[w] = sq; }
    __syncthreads();
    if (threadIdx.x == 0) {
        float ts = 0.f, tq = 0.f;
#pragma unroll
        for (int i = 0; i < 8; i++) { ts += rs[i]; tq += rq[i]; }
        float mean = ts * (1.0f/DD);
        s_mean = mean;
        s_rstd = rsqrtf(tq * (1.0f/DD) - mean*mean + EPSV);
    }
    __syncthreads();
    float mean = s_mean, rstd = s_rstd;
    __half* orow = out + (size_t)row * DD;
#pragma unroll
    for (int i = 0; i < 8; i++) {
        int d = threadIdx.x + i*256;
        orow[d] = __float2half(sc[d]*(v[i]-mean)*rstd + sh[d]);
    }
}

// ---------------- FP16 GEMM: C = A[M,K] @ Wt[N,K]^T (R10 layout) ----------------
#define KSTEP   64
#define ROWH    72
#define T_BYTES (128*ROWH*2)
#define STG_B   (2*T_BYTES)
#define G_SMEM  (3*STG_B)

// EPI 0: Ch=acc  EPI 1: Ch=half(acc+bias+Rf)  EPI 2: Ch=half(gelu(acc+bias))  EPI 3: Cf=acc+bias+Rh
template<int EPI>
__global__ __launch_bounds__(256, 2)
void mma_gemm(const __half* __restrict__ A, const __half* __restrict__ Bt,
              const float* __restrict__ bias, const float* __restrict__ Rf,
              const __half* __restrict__ Rh,
              float* __restrict__ Cf, __half* __restrict__ Ch, int N, int K) {
    extern __shared__ char dsm[];
    const int tid = threadIdx.x;
    const int lane = tid & 31;
    const int wid = tid >> 5;
    const int warpM = wid & 1;
    const int warpN = wid >> 1;
    const int m0 = blockIdx.y * 128;
    const int n0 = blockIdx.x * 128;
    const uint32_t sb = smem_u32(dsm);

    float acc[4][4][4];
#pragma unroll
    for (int i = 0; i < 4; i++)
#pragma unroll
        for (int j = 0; j < 4; j++)
#pragma unroll
            for (int u = 0; u < 4; u++) acc[i][j][u] = 0.f;

    const int NT = K / KSTEP;

    auto load_stage = [&](int s, int kk) {
        uint32_t ab = sb + s*STG_B;
        uint32_t bb = ab + T_BYTES;
#pragma unroll
        for (int i = 0; i < 4; i++) {
            int idx = i*256 + tid;
            int r = idx >> 3, c = idx & 7;
            cp_async16(ab + (r*ROWH + c*8)*2, A  + (size_t)(m0 + r)*K + kk + c*8);
            cp_async16(bb + (r*ROWH + c*8)*2, Bt + (size_t)(n0 + r)*K + kk + c*8);
        }
    };

    load_stage(0, 0); cp_commit();
    load_stage(1, KSTEP); cp_commit();

    const int j  = lane >> 3;
    const int rr = lane & 7;
    const uint32_t offA = ((warpM*64 + ((j&1)<<3) + rr) * ROWH + (j>>1)*8) * 2;
    const uint32_t offB = ((warpN*32 + (j>>1)*8  + rr) * ROWH + (j&1)*8) * 2;

    for (int t = 0; t < NT; t++) {
        cp_wait1();
        __syncthreads();
        if (t + 2 < NT) { load_stage((t+2)%3, (t+2)*KSTEP); cp_commit(); }

        int s = t % 3;
        uint32_t abase = sb + s*STG_B + offA;
        uint32_t bbase = sb + s*STG_B + T_BYTES + offB;
#pragma unroll
        for (int k16 = 0; k16 < 4; k16++) {
            uint32_t ka = abase + k16*32;
            uint32_t kb = bbase + k16*32;
            uint32_t afr[4][4];
#pragma unroll
            for (int mt = 0; mt < 4; mt++)
                ldmx4(afr[mt], ka + mt*(16*ROWH*2));
            uint32_t bfr[4][2];
            ldmx4(&bfr[0][0], kb);
            ldmx4(&bfr[2][0], kb + 16*ROWH*2);
#pragma unroll
            for (int mt = 0; mt < 4; mt++)
#pragma unroll
                for (int nt = 0; nt < 4; nt++)
                    mma_f16(acc[mt][nt], afr[mt], bfr[nt]);
        }
    }

#pragma unroll
    for (int mt = 0; mt < 4; mt++) {
#pragma unroll
        for (int half_ = 0; half_ < 2; half_++) {
            int m = m0 + warpM*64 + mt*16 + (lane >> 2) + half_*8;
#pragma unroll
            for (int nt = 0; nt < 4; nt++) {
                int n = n0 + warpN*32 + nt*8 + 2*(lane & 3);
                float v0 = acc[mt][nt][half_*2 + 0];
                float v1 = acc[mt][nt][half_*2 + 1];
                if (EPI == 0) {
                    *(__half2*)(Ch + (size_t)m*N + n) = __floats2half2_rn(v0, v1);
                } else if (EPI == 1) {
                    const float2 bb = *(const float2*)(bias + n);
                    const float2 rv = *(const float2*)(Rf + (size_t)m*N + n);
                    *(__half2*)(Ch + (size_t)m*N + n) =
                        __floats2half2_rn(v0 + bb.x + rv.x, v1 + bb.y + rv.y);
                } else if (EPI == 2) {
                    const float2 bb = *(const float2*)(bias + n);
                    *(__half2*)(Ch + (size_t)m*N + n) =
                        __floats2half2_rn(gelu_f(v0 + bb.x), gelu_f(v1 + bb.y));
                } else {
                    const float2 bb = *(const float2*)(bias + n);
                    __half2 rv = *(const __half2*)(Rh + (size_t)m*N + n);
                    float2 rf = __half22float2(rv);
                    float2 o; o.x = v0 + bb.x + rf.x; o.y = v1 + bb.y + rf.y;
                    *(float2*)(Cf + (size_t)m*N + n) = o;
                }
            }
        }
    }
}

// ---------------- causal flash attention (fp16, KV tile 128, P-in-regs, cp.async ring) ----------------
#define KVROWH 136
#define KV_TILE (128*KVROWH*2)             // 34816 B (K or V tile, 128 keys)
#define KV_STG  (2*KV_TILE)                // 69632 B per stage
#define Q_BYTES (128*KVROWH*2)             // 34816 B
#define ATT_SMEM (Q_BYTES + 2*KV_STG)      // 174080 B

__global__ __launch_bounds__(256, 1)
void attn_mma(const __half* __restrict__ Q, const __half* __restrict__ Kg,
              const __half* __restrict__ V, __half* __restrict__ O, int ld) {
    extern __shared__ __half hsm[];
    __half* Qs = hsm;
    const uint32_t sb = smem_u32(hsm);

    const int tid = threadIdx.x;
    const int lane = tid & 31;
    const int w = tid >> 5;
    const int r0 = lane >> 2;
    const int c0 = lane & 3;
    const int j  = lane >> 3;
    const int rr = lane & 7;
    const int q0 = blockIdx.x * 128;
    const int b = blockIdx.y >> 4;
    const int h = blockIdx.y & 15;
    const float rscale = 0.08838834764831845f;
    size_t ibase = ((size_t)b * SS) * ld + (size_t)h * HD;
    size_t obase = ((size_t)b * SS) * DD + (size_t)h * HD;

#pragma unroll
    for (int i = 0; i < 8; i++) {
        int idx = i*256 + tid;
        int r = idx >> 4, c = (idx & 15)*8;
        *(uint4*)(Qs + r*KVROWH + c) = *(const uint4*)(Q + ibase + (size_t)(q0 + r)*ld + c);
    }

    auto load_kv = [&](int kt) {
        int s = kt & 1;
        int k0 = kt * 128;
        uint32_t kb = sb + Q_BYTES + s*KV_STG;
        uint32_t vb = kb + KV_TILE;
#pragma unroll
        for (int i = 0; i < 8; i++) {
            int idx = i*256 + tid;
            int r = idx >> 4, c = (idx & 15)*8;
            cp_async16(kb + (r*KVROWH + c)*2, Kg + ibase + (size_t)(k0 + r)*ld + c);
            cp_async16(vb + (r*KVROWH + c)*2, V  + ibase + (size_t)(k0 + r)*ld + c);
        }
    };

    float acc[16][4];
#pragma unroll
    for (int i = 0; i < 16; i++)
#pragma unroll
        for (int u = 0; u < 4; u++) acc[i][u] = 0.f;
    float m0r = -1e30f, m1r = -1e30f, l0r = 0.f, l1r = 0.f;
    const int qi0 = q0 + w*16 + r0;
    const int qi1 = qi0 + 8;

    const uint32_t offQ = ((w*16 + ((j&1)<<3) + rr)*KVROWH + (j>>1)*8)*2;
    const uint32_t offK = (((j>>1)*8 + rr)*KVROWH + (j&1)*8)*2;
    const uint32_t offV = (((j&1)*8 + rr)*KVROWH + (j>>1)*8)*2;

    const int nkt = (q0 >> 7) + 1;
    load_kv(0); cp_commit();

    for (int kt = 0; kt < nkt; kt++) {
        int k0 = kt * 128;
        cp_wait0();
        __syncthreads();
        if (kt + 1 < nkt) { load_kv(kt + 1); cp_commit(); }

        int s = kt & 1;
        const uint32_t sK = sb + Q_BYTES + s*KV_STG;
        const uint32_t sV = sK + KV_TILE;

        // S = Q @ K^T : 128 q-rows x 128 keys; per warp sc[16][4]
        float sc[16][4];
#pragma unroll
        for (int nt = 0; nt < 16; nt++)
#pragma unroll
            for (int u = 0; u < 4; u++) sc[nt][u] = 0.f;
#pragma unroll
        for (int kc = 0; kc < 8; kc++) {
            uint32_t a[4];
            ldmx4(a, sb + offQ + kc*32);
#pragma unroll
            for (int g = 0; g < 8; g++) {
                uint32_t bb[4];
                ldmx4(bb, sK + offK + kc*32 + g*(16*KVROWH*2));
                mma_f16(sc[2*g    ], a, bb);
                mma_f16(sc[2*g + 1], a, bb + 2);
            }
        }
#pragma unroll
        for (int nt = 0; nt < 16; nt++)
#pragma unroll
            for (int u = 0; u < 4; u++) sc[nt][u] *= rscale;
        if (k0 + 127 > qi0) {
#pragma unroll
            for (int nt = 0; nt < 16; nt++) {
                int cj = k0 + nt*8 + 2*c0;
                if (cj     > qi0) sc[nt][0] = -1e30f;
                if (cj + 1 > qi0) sc[nt][1] = -1e30f;
                if (cj     > qi1) sc[nt][2] = -1e30f;
                if (cj + 1 > qi1) sc[nt][3] = -1e30f;
            }
        }
        // online softmax
        float tm0 = -1e30f, tm1 = -1e30f;
#pragma unroll
        for (int nt = 0; nt < 16; nt++) {
            tm0 = fmaxf(tm0, fmaxf(sc[nt][0], sc[nt][1]));
            tm1 = fmaxf(tm1, fmaxf(sc[nt][2], sc[nt][3]));
        }
        tm0 = fmaxf(tm0, __shfl_xor_sync(0xFFFFFFFFu, tm0, 1));
        tm0 = fmaxf(tm0, __shfl_xor_sync(0xFFFFFFFFu, tm0, 2));
        tm1 = fmaxf(tm1, __shfl_xor_sync(0xFFFFFFFFu, tm1, 1));
        tm1 = fmaxf(tm1, __shfl_xor_sync(0xFFFFFFFFu, tm1, 2));
        float mn0 = fmaxf(m0r, tm0), f0 = __expf(m0r - mn0);
        float mn1 = fmaxf(m1r, tm1), f1 = __expf(m1r - mn1);
        float ps0 = 0.f, ps1 = 0.f;
#pragma unroll
        for (int nt = 0; nt < 16; nt++) {
            sc[nt][0] = __expf(sc[nt][0] - mn0);
            sc[nt][1] = __expf(sc[nt][1] - mn0);
            sc[nt][2] = __expf(sc[nt][2] - mn1);
            sc[nt][3] = __expf(sc[nt][3] - mn1);
            ps0 += sc[nt][0] + sc[nt][1];
            ps1 += sc[nt][2] + sc[nt][3];
        }
        ps0 += __shfl_xor_sync(0xFFFFFFFFu, ps0, 1);
        ps0 += __shfl_xor_sync(0xFFFFFFFFu, ps0, 2);
        ps1 += __shfl_xor_sync(0xFFFFFFFFu, ps1, 1);
        ps1 += __shfl_xor_sync(0xFFFFFFFFu, ps1, 2);
        l0r = l0r*f0 + ps0; m0r = mn0;
        l1r = l1r*f1 + ps1; m1r = mn1;
#pragma unroll
        for (int nt = 0; nt < 16; nt++) {
            acc[nt][0] *= f0; acc[nt][1] *= f0;
            acc[nt][2] *= f1; acc[nt][3] *= f1;
        }
        // O += P @ V : 128 keys = 8 k16 chunks, P A-frags from sc registers
#pragma unroll
        for (int g = 0; g < 8; g++) {
            uint32_t a[4];
            a[0] = pack_h2(sc[2*g  ][0], sc[2*g  ][1]);
            a[1] = pack_h2(sc[2*g  ][2], sc[2*g  ][3]);
            a[2] = pack_h2(sc[2*g+1][0], sc[2*g+1][1]);
            a[3] = pack_h2(sc[2*g+1][2], sc[2*g+1][3]);
#pragma unroll
            for (int g2 = 0; g2 < 8; g2++) {
                uint32_t bb[4];
                ldmx4t(bb, sV + offV + g*(16*KVROWH*2) + g2*32);
                mma_f16(acc[2*g2    ], a, bb);
                mma_f16(acc[2*g2 + 1], a, bb + 2);
            }
        }
    }

    float inv0 = 1.0f / l0r, inv1 = 1.0f / l1r;
#pragma unroll
    for (int nt = 0; nt < 16; nt++) {
        int n = nt*8 + 2*c0;
        *(__half2*)(O + obase + (size_t)qi0*DD + n) = __floats2half2_rn(acc[nt][0]*inv0, acc[nt][1]*inv0);
        *(__half2*)(O + obase + (size_t)qi1*DD + n) = __floats2half2_rn(acc[nt][2]*inv1, acc[nt][3]*inv1);
    }
}

// ---------------- launch ----------------
extern "C" void kernel_launch(void* const* d_in, const int* in_sizes, int n_in,
                              void* d_out, int out_size) {
    const float* x    = (const float*)d_in[0];
    const float* Wq   = (const float*)d_in[1];
    const float* Wk   = (const float*)d_in[2];
    const float* Wv   = (const float*)d_in[3];
    const float* Wo   = (const float*)d_in[4];
    const float* bo   = (const float*)d_in[5];
    const float* ln1s = (const float*)d_in[6];
    const float* ln1b = (const float*)d_in[7];
    const float* ln2s = (const float*)d_in[8];
    const float* ln2b = (const float*)d_in[9];
    const float* W1   = (const float*)d_in[10];
    const float* b1   = (const float*)d_in[11];
    const float* W2   = (const float*)d_in[12];
    const float* b2   = (const float*)d_in[13];
    float* out = (float*)d_out;

    __half *xn, *qkv, *ctx, *h, *ff, *wqkvT, *woT, *w1T, *w2T;
    cudaGetSymbolAddress((void**)&xn,    g_xn);
    cudaGetSymbolAddress((void**)&qkv,   g_qkv);
    cudaGetSymbolAddress((void**)&ctx,   g_ctx);
    cudaGetSymbolAddress((void**)&h,     g_h);
    cudaGetSymbolAddress((void**)&ff,    g_ff);
    cudaGetSymbolAddress((void**)&wqkvT, g_wqkvT);
    cudaGetSymbolAddress((void**)&woT,   g_woT);
    cudaGetSymbolAddress((void**)&w1T,   g_w1T);
    cudaGetSymbolAddress((void**)&w2T,   g_w2T);

    cudaFuncSetAttribute(attn_mma, cudaFuncAttributeMaxDynamicSharedMemorySize, ATT_SMEM);
    cudaFuncSetAttribute(mma_gemm<0>, cudaFuncAttributeMaxDynamicSharedMemorySize, G_SMEM);
    cudaFuncSetAttribute(mma_gemm<1>, cudaFuncAttributeMaxDynamicSharedMemorySize, G_SMEM);
    cudaFuncSetAttribute(mma_gemm<2>, cudaFuncAttributeMaxDynamicSharedMemorySize, G_SMEM);
    cudaFuncSetAttribute(mma_gemm<3>, cudaFuncAttributeMaxDynamicSharedMemorySize, G_SMEM);

    // weight transposes (64x64 tiles)
    transpose_half<<<dim3(DD/64,  DD/64), 256>>>(Wq, wqkvT, DD, DD, 0,    DD);
    transpose_half<<<dim3(DD/64,  DD/64), 256>>>(Wk, wqkvT, DD, DD, 2048, DD);
    transpose_half<<<dim3(DD/64,  DD/64), 256>>>(Wv, wqkvT, DD, DD, 4096, DD);
    transpose_half<<<dim3(DD/64,  DD/64), 256>>>(Wo, woT, DD, DD, 0, DD);
    transpose_half<<<dim3(DFF/64, DD/64), 256>>>(W1, w1T, DD, DFF, 0, DD);
    transpose_half<<<dim3(DD/64, DFF/64), 256>>>(W2, w2T, DFF, DD, 0, DFF);

    ln_kernel<float><<<MROW, 256>>>(x, ln1s, ln1b, xn);
    mma_gemm<0><<<dim3(QS/128, MROW/128), 256, G_SMEM>>>(
        xn, wqkvT, nullptr, nullptr, nullptr, nullptr, qkv, QS, DD);
    attn_mma<<<dim3(SS/128, BB*HH), 256, ATT_SMEM>>>(qkv, qkv + 2048, qkv + 4096, ctx, QS);
    mma_gemm<1><<<dim3(DD/128, MROW/128), 256, G_SMEM>>>(
        ctx, woT, bo, x, nullptr, nullptr, h, DD, DD);
    ln_kernel<__half><<<MROW, 256>>>(h, ln2s, ln2b, xn);
    mma_gemm<2><<<dim3(DFF/128, MROW/128), 256, G_SMEM>>>(
        xn, w1T, b1, nullptr, nullptr, nullptr, ff, DFF, DD);
    mma_gemm<3><<<dim3(DD/128, MROW/128), 256, G_SMEM>>>(
        ff, w2T, b2, nullptr, h, out, nullptr, DD, DFF);
}

// round 15
// speedup vs baseline: 1.0473x; 1.0120x over previous
#include <cuda_runtime.h>
#include <cuda_fp16.h>
#include <math.h>
#include <stdint.h>

#define BB   2
#define SS   2048
#define DD   2048
#define HH   16
#define HD   128
#define DFF  8192
#define MROW 4096
#define QS   6144
#define EPSV 1e-5f

// ---------------- scratch ----------------
static __device__ __half g_xn  [(size_t)MROW*DD];
static __device__ __half g_qkv [(size_t)MROW*QS];
static __device__ __half g_ctx [(size_t)MROW*DD];
static __device__ __half g_h   [(size_t)MROW*DD];
static __device__ __half g_ff  [(size_t)MROW*DFF];
static __device__ __half g_wqkvT[(size_t)QS*DD];
static __device__ __half g_woT  [(size_t)DD*DD];
static __device__ __half g_w1T  [(size_t)DFF*DD];
static __device__ __half g_w2T  [(size_t)DD*DFF];

// ---------------- helpers ----------------
__device__ __forceinline__ uint32_t smem_u32(const void* p) {
    uint32_t a;
    asm("{ .reg .u64 t; cvta.to.shared.u64 t, %1; cvt.u32.u64 %0, t; }" : "=r"(a) : "l"(p));
    return a;
}
__device__ __forceinline__ void cp_async16(uint32_t s, const void* g) {
    asm volatile("cp.async.cg.shared.global [%0], [%1], 16;" :: "r"(s), "l"(g));
}
__device__ __forceinline__ void cp_commit() {
    asm volatile("cp.async.commit_group;" ::: "memory");
}
__device__ __forceinline__ void cp_wait1() {
    asm volatile("cp.async.wait_group 1;" ::: "memory");
}
__device__ __forceinline__ void cp_wait0() {
    asm volatile("cp.async.wait_group 0;" ::: "memory");
}
__device__ __forceinline__ void ldmx4(uint32_t* r, uint32_t addr) {
    asm volatile("ldmatrix.sync.aligned.m8n8.x4.shared.b16 {%0,%1,%2,%3}, [%4];"
        : "=r"(r[0]), "=r"(r[1]), "=r"(r[2]), "=r"(r[3]) : "r"(addr));
}
__device__ __forceinline__ void ldmx4t(uint32_t* r, uint32_t addr) {
    asm volatile("ldmatrix.sync.aligned.m8n8.x4.trans.shared.b16 {%0,%1,%2,%3}, [%4];"
        : "=r"(r[0]), "=r"(r[1]), "=r"(r[2]), "=r"(r[3]) : "r"(addr));
}
__device__ __forceinline__ void mma_f16(float* c, const uint32_t* a, const uint32_t* b) {
    asm volatile("mma.sync.aligned.m16n8k16.row.col.f32.f16.f16.f32 "
        "{%0,%1,%2,%3}, {%4,%5,%6,%7}, {%8,%9}, {%0,%1,%2,%3};"
        : "+f"(c[0]), "+f"(c[1]), "+f"(c[2]), "+f"(c[3])
        : "r"(a[0]), "r"(a[1]), "r"(a[2]), "r"(a[3]), "r"(b[0]), "r"(b[1]));
}
__device__ __forceinline__ uint32_t pack_h2(float a, float b) {
    __half2 t = __floats2half2_rn(a, b);
    return *reinterpret_cast<uint32_t*>(&t);
}
__device__ __forceinline__ float gelu_f(float x) {
    float x3 = x*x*x;
    return 0.5f * x * (1.0f + tanhf(0.79788456080286536f * (x + 0.044715f*x3)));
}

// ---------------- weight transpose -> fp16 (64x64 tiles) ----------------
__global__ __launch_bounds__(256)
void transpose_half(const float* __restrict__ W, __half* __restrict__ Wt,
                    int K, int N, int rowOff, int ldOut) {
    __shared__ float t[64][65];
    int k0 = blockIdx.y * 64, n0 = blockIdx.x * 64;
    int tx = threadIdx.x;
#pragma unroll
    for (int i = 0; i < 4; i++) {
        int idx = i*256 + tx;
        int r = idx >> 4, c4 = (idx & 15)*4;
        float4 v = *(const float4*)(W + (size_t)(k0 + r)*N + n0 + c4);
        t[r][c4] = v.x; t[r][c4+1] = v.y; t[r][c4+2] = v.z; t[r][c4+3] = v.w;
    }
    __syncthreads();
#pragma unroll
    for (int i = 0; i < 2; i++) {
        int idx = i*256 + tx;
        int r = idx >> 3, c8 = (idx & 7)*8;
        __half h[8];
#pragma unroll
        for (int u = 0; u < 8; u++) h[u] = __float2half(t[c8 + u][r]);
        *(uint4*)(Wt + (size_t)(rowOff + n0 + r)*ldOut + k0 + c8) = *(uint4*)h;
    }
}

// ---------------- LayerNorm (T in -> fp16 out) ----------------
template<typename T>
__global__ __launch_bounds__(256)
void ln_kernel(const T* __restrict__ x, const float* __restrict__ sc,
               const float* __restrict__ sh, __half* __restrict__ out) {
    int row = blockIdx.x;
    const T* xr = x + (size_t)row * DD;
    float v[8];
    float s = 0.f, sq = 0.f;
#pragma unroll
    for (int i = 0; i < 8; i++) {
        v[i] = (float)xr[threadIdx.x + i*256];
        s += v[i]; sq += v[i]*v[i];
    }
    __shared__ float rs[8], rq[8];
    __shared__ float s_mean, s_rstd;
#pragma unroll
    for (int o = 16; o > 0; o >>= 1) {
        s  += __shfl_down_sync(0xFFFFFFFFu, s,  o);
        sq += __shfl_down_sync(0xFFFFFFFFu, sq, o);
    }
    int w = threadIdx.x >> 5;
    if ((threadIdx.x & 31) == 0) { rs[w] = s; rq[w] = sq; }
    __syncthreads();
    if (threadIdx.x == 0) {
        float ts = 0.f, tq = 0.f;
#pragma unroll
        for (int i = 0; i < 8; i++) { ts += rs[i]; tq += rq[i]; }
        float mean = ts * (1.0f/DD);
        s_mean = mean;
        s_rstd = rsqrtf(tq * (1.0f/DD) - mean*mean + EPSV);
    }
    __syncthreads();
    float mean = s_mean, rstd = s_rstd;
    __half* orow = out + (size_t)row * DD;
#pragma unroll
    for (int i = 0; i < 8; i++) {
        int d = threadIdx.x + i*256;
        orow[d] = __float2half(sc[d]*(v[i]-mean)*rstd + sh[d]);
    }
}

// ---------------- FP16 GEMM: C = A[M,K] @ Wt[N,K]^T (group-M swizzled raster) ----------------
#define KSTEP   64
#define ROWH    72
#define T_BYTES (128*ROWH*2)
#define STG_B   (2*T_BYTES)
#define G_SMEM  (3*STG_B)
#define GRP_M   8

// EPI 0: Ch=acc  EPI 1: Ch=half(acc+bias+Rf)  EPI 2: Ch=half(gelu(acc+bias))  EPI 3: Cf=acc+bias+Rh
template<int EPI>
__global__ __launch_bounds__(256, 2)
void mma_gemm(const __half* __restrict__ A, const __half* __restrict__ Bt,
              const float* __restrict__ bias, const float* __restrict__ Rf,
              const __half* __restrict__ Rh,
              float* __restrict__ Cf, __half* __restrict__ Ch, int N, int K) {
    extern __shared__ char dsm[];
    const int tid = threadIdx.x;
    const int lane = tid & 31;
    const int wid = tid >> 5;
    const int warpM = wid & 1;
    const int warpN = wid >> 1;

    // group-M swizzled rasterization: 8 consecutive CTAs share one B tile
    const int nBlkN = gridDim.x, nBlkM = gridDim.y;
    int bid = blockIdx.y * nBlkN + blockIdx.x;
    int perGrp = GRP_M * nBlkN;
    int grp = bid / perGrp;
    int rem = bid - grp * perGrp;
    int gsz = nBlkM - grp*GRP_M; if (gsz > GRP_M) gsz = GRP_M;
    const int m0 = (grp*GRP_M + rem % gsz) * 128;
    const int n0 = (rem / gsz) * 128;

    const uint32_t sb = smem_u32(dsm);

    float acc[4][4][4];
#pragma unroll
    for (int i = 0; i < 4; i++)
#pragma unroll
        for (int j = 0; j < 4; j++)
#pragma unroll
            for (int u = 0; u < 4; u++) acc[i][j][u] = 0.f;

    const int NT = K / KSTEP;

    auto load_stage = [&](int s, int kk) {
        uint32_t ab = sb + s*STG_B;
        uint32_t bb = ab + T_BYTES;
#pragma unroll
        for (int i = 0; i < 4; i++) {
            int idx = i*256 + tid;
            int r = idx >> 3, c = idx & 7;
            cp_async16(ab + (r*ROWH + c*8)*2, A  + (size_t)(m0 + r)*K + kk + c*8);
            cp_async16(bb + (r*ROWH + c*8)*2, Bt + (size_t)(n0 + r)*K + kk + c*8);
        }
    };

    load_stage(0, 0); cp_commit();
    load_stage(1, KSTEP); cp_commit();

    const int j  = lane >> 3;
    const int rr = lane & 7;
    const uint32_t offA = ((warpM*64 + ((j&1)<<3) + rr) * ROWH + (j>>1)*8) * 2;
    const uint32_t offB = ((warpN*32 + (j>>1)*8  + rr) * ROWH + (j&1)*8) * 2;

    for (int t = 0; t < NT; t++) {
        cp_wait1();
        __syncthreads();
        if (t + 2 < NT) { load_stage((t+2)%3, (t+2)*KSTEP); cp_commit(); }

        int s = t % 3;
        uint32_t abase = sb + s*STG_B + offA;
        uint32_t bbase = sb + s*STG_B + T_BYTES + offB;
#pragma unroll
        for (int k16 = 0; k16 < 4; k16++) {
            uint32_t ka = abase + k16*32;
            uint32_t kb = bbase + k16*32;
            uint32_t afr[4][4];
#pragma unroll
            for (int mt = 0; mt < 4; mt++)
                ldmx4(afr[mt], ka + mt*(16*ROWH*2));
            uint32_t bfr[4][2];
            ldmx4(&bfr[0][0], kb);
            ldmx4(&bfr[2][0], kb + 16*ROWH*2);
#pragma unroll
            for (int mt = 0; mt < 4; mt++)
#pragma unroll
                for (int nt = 0; nt < 4; nt++)
                    mma_f16(acc[mt][nt], afr[mt], bfr[nt]);
        }
    }

#pragma unroll
    for (int mt = 0; mt < 4; mt++) {
#pragma unroll
        for (int half_ = 0; half_ < 2; half_++) {
            int m = m0 + warpM*64 + mt*16 + (lane >> 2) + half_*8;
#pragma unroll
            for (int nt = 0; nt < 4; nt++) {
                int n = n0 + warpN*32 + nt*8 + 2*(lane & 3);
                float v0 = acc[mt][nt][half_*2 + 0];
                float v1 = acc[mt][nt][half_*2 + 1];
                if (EPI == 0) {
                    *(__half2*)(Ch + (size_t)m*N + n) = __floats2half2_rn(v0, v1);
                } else if (EPI == 1) {
                    const float2 bb = *(const float2*)(bias + n);
                    const float2 rv = *(const float2*)(Rf + (size_t)m*N + n);
                    *(__half2*)(Ch + (size_t)m*N + n) =
                        __floats2half2_rn(v0 + bb.x + rv.x, v1 + bb.y + rv.y);
                } else if (EPI == 2) {
                    const float2 bb = *(const float2*)(bias + n);
                    *(__half2*)(Ch + (size_t)m*N + n) =
                        __floats2half2_rn(gelu_f(v0 + bb.x), gelu_f(v1 + bb.y));
                } else {
                    const float2 bb = *(const float2*)(bias + n);
                    __half2 rv = *(const __half2*)(Rh + (size_t)m*N + n);
                    float2 rf = __half22float2(rv);
                    float2 o; o.x = v0 + bb.x + rf.x; o.y = v1 + bb.y + rf.y;
                    *(float2*)(Cf + (size_t)m*N + n) = o;
                }
            }
        }
    }
}

// ---------------- causal flash attention (fp16, KV tile 128, exp2 softmax) ----------------
#define KVROWH 136
#define KV_TILE (128*KVROWH*2)
#define KV_STG  (2*KV_TILE)
#define Q_BYTES (128*KVROWH*2)
#define ATT_SMEM (Q_BYTES + 2*KV_STG)

__global__ __launch_bounds__(256, 1)
void attn_mma(const __half* __restrict__ Q, const __half* __restrict__ Kg,
              const __half* __restrict__ V, __half* __restrict__ O, int ld) {
    extern __shared__ __half hsm[];
    __half* Qs = hsm;
    const uint32_t sb = smem_u32(hsm);

    const int tid = threadIdx.x;
    const int lane = tid & 31;
    const int w = tid >> 5;
    const int r0 = lane >> 2;
    const int c0 = lane & 3;
    const int j  = lane >> 3;
    const int rr = lane & 7;
    const int q0 = blockIdx.x * 128;
    const int b = blockIdx.y >> 4;
    const int h = blockIdx.y & 15;
    // 1/sqrt(128) * log2(e)  (exp2-domain softmax)
    const float rscale = 0.12751677003257157f;
    size_t ibase = ((size_t)b * SS) * ld + (size_t)h * HD;
    size_t obase = ((size_t)b * SS) * DD + (size_t)h * HD;

#pragma unroll
    for (int i = 0; i < 8; i++) {
        int idx = i*256 + tid;
        int r = idx >> 4, c = (idx & 15)*8;
        *(uint4*)(Qs + r*KVROWH + c) = *(const uint4*)(Q + ibase + (size_t)(q0 + r)*ld + c);
    }

    auto load_kv = [&](int kt) {
        int s = kt & 1;
        int k0 = kt * 128;
        uint32_t kb = sb + Q_BYTES + s*KV_STG;
        uint32_t vb = kb + KV_TILE;
#pragma unroll
        for (int i = 0; i < 8; i++) {
            int idx = i*256 + tid;
            int r = idx >> 4, c = (idx & 15)*8;
            cp_async16(kb + (r*KVROWH + c)*2, Kg + ibase + (size_t)(k0 + r)*ld + c);
            cp_async16(vb + (r*KVROWH + c)*2, V  + ibase + (size_t)(k0 + r)*ld + c);
        }
    };

    float acc[16][4];
#pragma unroll
    for (int i = 0; i < 16; i++)
#pragma unroll
        for (int u = 0; u < 4; u++) acc[i][u] = 0.f;
    float m0r = -1e30f, m1r = -1e30f, l0r = 0.f, l1r = 0.f;
    const int qi0 = q0 + w*16 + r0;
    const int qi1 = qi0 + 8;

    const uint32_t offQ = ((w*16 + ((j&1)<<3) + rr)*KVROWH + (j>>1)*8)*2;
    const uint32_t offK = (((j>>1)*8 + rr)*KVROWH + (j&1)*8)*2;
    const uint32_t offV = (((j&1)*8 + rr)*KVROWH + (j>>1)*8)*2;

    const int nkt = (q0 >> 7) + 1;
    load_kv(0); cp_commit();

    for (int kt = 0; kt < nkt; kt++) {
        int k0 = kt * 128;
        cp_wait0();
        __syncthreads();
        if (kt + 1 < nkt) { load_kv(kt + 1); cp_commit(); }

        int s = kt & 1;
        const uint32_t sK = sb + Q_BYTES + s*KV_STG;
        const uint32_t sV = sK + KV_TILE;

        float sc[16][4];
#pragma unroll
        for (int nt = 0; nt < 16; nt++)
#pragma unroll
            for (int u = 0; u < 4; u++) sc[nt][u] = 0.f;
#pragma unroll
        for (int kc = 0; kc < 8; kc++) {
            uint32_t a[4];
            ldmx4(a, sb + offQ + kc*32);
#pragma unroll
            for (int g = 0; g < 8; g++) {
                uint32_t bb[4];
                ldmx4(bb, sK + offK + kc*32 + g*(16*KVROWH*2));
                mma_f16(sc[2*g    ], a, bb);
                mma_f16(sc[2*g + 1], a, bb + 2);
            }
        }
#pragma unroll
        for (int nt = 0; nt < 16; nt++)
#pragma unroll
            for (int u = 0; u < 4; u++) sc[nt][u] *= rscale;
        if (k0 + 127 > qi0) {
#pragma unroll
            for (int nt = 0; nt < 16; nt++) {
                int cj = k0 + nt*8 + 2*c0;
                if (cj     > qi0) sc[nt][0] = -1e30f;
                if (cj + 1 > qi0) sc[nt][1] = -1e30f;
                if (cj     > qi1) sc[nt][2] = -1e30f;
                if (cj + 1 > qi1) sc[nt][3] = -1e30f;
            }
        }
        float tm0 = -1e30f, tm1 = -1e30f;
#pragma unroll
        for (int nt = 0; nt < 16; nt++) {
            tm0 = fmaxf(tm0, fmaxf(sc[nt][0], sc[nt][1]));
            tm1 = fmaxf(tm1, fmaxf(sc[nt][2], sc[nt][3]));
        }
        tm0 = fmaxf(tm0, __shfl_xor_sync(0xFFFFFFFFu, tm0, 1));
        tm0 = fmaxf(tm0, __shfl_xor_sync(0xFFFFFFFFu, tm0, 2));
        tm1 = fmaxf(tm1, __shfl_xor_sync(0xFFFFFFFFu, tm1, 1));
        tm1 = fmaxf(tm1, __shfl_xor_sync(0xFFFFFFFFu, tm1, 2));
        float mn0 = fmaxf(m0r, tm0), f0 = exp2f(m0r - mn0);
        float mn1 = fmaxf(m1r, tm1), f1 = exp2f(m1r - mn1);
        float ps0 = 0.f, ps1 = 0.f;
#pragma unroll
        for (int nt = 0; nt < 16; nt++) {
            sc[nt][0] = exp2f(sc[nt][0] - mn0);
            sc[nt][1] = exp2f(sc[nt][1] - mn0);
            sc[nt][2] = exp2f(sc[nt][2] - mn1);
            sc[nt][3] = exp2f(sc[nt][3] - mn1);
            ps0 += sc[nt][0] + sc[nt][1];
            ps1 += sc[nt][2] + sc[nt][3];
        }
        ps0 += __shfl_xor_sync(0xFFFFFFFFu, ps0, 1);
        ps0 += __shfl_xor_sync(0xFFFFFFFFu, ps0, 2);
        ps1 += __shfl_xor_sync(0xFFFFFFFFu, ps1, 1);
        ps1 += __shfl_xor_sync(0xFFFFFFFFu, ps1, 2);
        l0r = l0r*f0 + ps0; m0r = mn0;
        l1r = l1r*f1 + ps1; m1r = mn1;
#pragma unroll
        for (int nt = 0; nt < 16; nt++) {
            acc[nt][0] *= f0; acc[nt][1] *= f0;
            acc[nt][2] *= f1; acc[nt][3] *= f1;
        }
#pragma unroll
        for (int g = 0; g < 8; g++) {
            uint32_t a[4];
            a[0] = pack_h2(sc[2*g  ][0], sc[2*g  ][1]);
            a[1] = pack_h2(sc[2*g  ][2], sc[2*g  ][3]);
            a[2] = pack_h2(sc[2*g+1][0], sc[2*g+1][1]);
            a[3] = pack_h2(sc[2*g+1][2], sc[2*g+1][3]);
#pragma unroll
            for (int g2 = 0; g2 < 8; g2++) {
                uint32_t bb[4];
                ldmx4t(bb, sV + offV + g*(16*KVROWH*2) + g2*32);
                mma_f16(acc[2*g2    ], a, bb);
                mma_f16(acc[2*g2 + 1], a, bb + 2);
            }
        }
    }

    float inv0 = 1.0f / l0r, inv1 = 1.0f / l1r;
#pragma unroll
    for (int nt = 0; nt < 16; nt++) {
        int n = nt*8 + 2*c0;
        *(__half2*)(O + obase + (size_t)qi0*DD + n) = __floats2half2_rn(acc[nt][0]*inv0, acc[nt][1]*inv0);
        *(__half2*)(O + obase + (size_t)qi1*DD + n) = __floats2half2_rn(acc[nt][2]*inv1, acc[nt][3]*inv1);
    }
}

// ---------------- launch ----------------
extern "C" void kernel_launch(void* const* d_in, const int* in_sizes, int n_in,
                              void* d_out, int out_size) {
    const float* x    = (const float*)d_in[0];
    const float* Wq   = (const float*)d_in[1];
    const float* Wk   = (const float*)d_in[2];
    const float* Wv   = (const float*)d_in[3];
    const float* Wo   = (const float*)d_in[4];
    const float* bo   = (const float*)d_in[5];
    const float* ln1s = (const float*)d_in[6];
    const float* ln1b = (const float*)d_in[7];
    const float* ln2s = (const float*)d_in[8];
    const float* ln2b = (const float*)d_in[9];
    const float* W1   = (const float*)d_in[10];
    const float* b1   = (const float*)d_in[11];
    const float* W2   = (const float*)d_in[12];
    const float* b2   = (const float*)d_in[13];
    float* out = (float*)d_out;

    __half *xn, *qkv, *ctx, *h, *ff, *wqkvT, *woT, *w1T, *w2T;
    cudaGetSymbolAddress((void**)&xn,    g_xn);
    cudaGetSymbolAddress((void**)&qkv,   g_qkv);
    cudaGetSymbolAddress((void**)&ctx,   g_ctx);
    cudaGetSymbolAddress((void**)&h,     g_h);
    cudaGetSymbolAddress((void**)&ff,    g_ff);
    cudaGetSymbolAddress((void**)&wqkvT, g_wqkvT);
    cudaGetSymbolAddress((void**)&woT,   g_woT);
    cudaGetSymbolAddress((void**)&w1T,   g_w1T);
    cudaGetSymbolAddress((void**)&w2T,   g_w2T);

    cudaFuncSetAttribute(attn_mma, cudaFuncAttributeMaxDynamicSharedMemorySize, ATT_SMEM);
    cudaFuncSetAttribute(mma_gemm<0>, cudaFuncAttributeMaxDynamicSharedMemorySize, G_SMEM);
    cudaFuncSetAttribute(mma_gemm<1>, cudaFuncAttributeMaxDynamicSharedMemorySize, G_SMEM);
    cudaFuncSetAttribute(mma_gemm<2>, cudaFuncAttributeMaxDynamicSharedMemorySize, G_SMEM);
    cudaFuncSetAttribute(mma_gemm<3>, cudaFuncAttributeMaxDynamicSharedMemorySize, G_SMEM);

    transpose_half<<<dim3(DD/64,  DD/64), 256>>>(Wq, wqkvT, DD, DD, 0,    DD);
    transpose_half<<<dim3(DD/64,  DD/64), 256>>>(Wk, wqkvT, DD, DD, 2048, DD);
    transpose_half<<<dim3(DD/64,  DD/64), 256>>>(Wv, wqkvT, DD, DD, 4096, DD);
    transpose_half<<<dim3(DD/64,  DD/64), 256>>>(Wo, woT, DD, DD, 0, DD);
    transpose_half<<<dim3(DFF/64, DD/64), 256>>>(W1, w1T, DD, DFF, 0, DD);
    transpose_half<<<dim3(DD/64, DFF/64), 256>>>(W2, w2T, DFF, DD, 0, DFF);

    ln_kernel<float><<<MROW, 256>>>(x, ln1s, ln1b, xn);
    mma_gemm<0><<<dim3(QS/128, MROW/128), 256, G_SMEM>>>(
        xn, wqkvT, nullptr, nullptr, nullptr, nullptr, qkv, QS, DD);
    attn_mma<<<dim3(SS/128, BB*HH), 256, ATT_SMEM>>>(qkv, qkv + 2048, qkv + 4096, ctx, QS);
    mma_gemm<1><<<dim3(DD/128, MROW/128), 256, G_SMEM>>>(
        ctx, woT, bo, x, nullptr, nullptr, h, DD, DD);
    ln_kernel<__half><<<MROW, 256>>>(h, ln2s, ln2b, xn);
    mma_gemm<2><<<dim3(DFF/128, MROW/128), 256, G_SMEM>>>(
        xn, w1T, b1, nullptr, nullptr, nullptr, ff, DFF, DD);
    mma_gemm<3><<<dim3(DD/128, MROW/128), 256, G_SMEM>>>(
        ff, w2T, b2, nullptr, h, out, nullptr, DD, DFF);
}

// round 16
// speedup vs baseline: 1.0544x; 1.0068x over previous
#include <cuda_runtime.h>
#include <cuda_fp16.h>
#include <math.h>
#include <stdint.h>

#define BB   2
#define SS   2048
#define DD   2048
#define HH   16
#define HD   128
#define DFF  8192
#define MROW 4096
#define QS   6144
#define EPSV 1e-5f

// ---------------- scratch ----------------
static __device__ __half g_xn  [(size_t)MROW*DD];
static __device__ __half g_qkv [(size_t)MROW*QS];
static __device__ __half g_ctx [(size_t)MROW*DD];
static __device__ __half g_h   [(size_t)MROW*DD];
static __device__ __half g_ff  [(size_t)MROW*DFF];
static __device__ __half g_wqkvT[(size_t)QS*DD];
static __device__ __half g_woT  [(size_t)DD*DD];
static __device__ __half g_w1T  [(size_t)DFF*DD];
static __device__ __half g_w2T  [(size_t)DD*DFF];

// ---------------- helpers ----------------
__device__ __forceinline__ uint32_t smem_u32(const void* p) {
    uint32_t a;
    asm("{ .reg .u64 t; cvta.to.shared.u64 t, %1; cvt.u32.u64 %0, t; }" : "=r"(a) : "l"(p));
    return a;
}
__device__ __forceinline__ void cp_async16(uint32_t s, const void* g) {
    asm volatile("cp.async.cg.shared.global [%0], [%1], 16;" :: "r"(s), "l"(g));
}
__device__ __forceinline__ void cp_commit() {
    asm volatile("cp.async.commit_group;" ::: "memory");
}
__device__ __forceinline__ void cp_wait1() {
    asm volatile("cp.async.wait_group 1;" ::: "memory");
}
__device__ __forceinline__ void cp_wait0() {
    asm volatile("cp.async.wait_group 0;" ::: "memory");
}
__device__ __forceinline__ void ldmx4(uint32_t* r, uint32_t addr) {
    asm volatile("ldmatrix.sync.aligned.m8n8.x4.shared.b16 {%0,%1,%2,%3}, [%4];"
        : "=r"(r[0]), "=r"(r[1]), "=r"(r[2]), "=r"(r[3]) : "r"(addr));
}
__device__ __forceinline__ void ldmx4t(uint32_t* r, uint32_t addr) {
    asm volatile("ldmatrix.sync.aligned.m8n8.x4.trans.shared.b16 {%0,%1,%2,%3}, [%4];"
        : "=r"(r[0]), "=r"(r[1]), "=r"(r[2]), "=r"(r[3]) : "r"(addr));
}
__device__ __forceinline__ void mma_f16(float* c, const uint32_t* a, const uint32_t* b) {
    asm volatile("mma.sync.aligned.m16n8k16.row.col.f32.f16.f16.f32 "
        "{%0,%1,%2,%3}, {%4,%5,%6,%7}, {%8,%9}, {%0,%1,%2,%3};"
        : "+f"(c[0]), "+f"(c[1]), "+f"(c[2]), "+f"(c[3])
        : "r"(a[0]), "r"(a[1]), "r"(a[2]), "r"(a[3]), "r"(b[0]), "r"(b[1]));
}
__device__ __forceinline__ uint32_t pack_h2(float a, float b) {
    __half2 t = __floats2half2_rn(a, b);
    return *reinterpret_cast<uint32_t*>(&t);
}
__device__ __forceinline__ float ex2f(float x) {
    float r;
    asm("ex2.approx.f32 %0, %1;" : "=f"(r) : "f"(x));
    return r;
}
__device__ __forceinline__ float tanh_hw(float x) {
    float r;
    asm("tanh.approx.f32 %0, %1;" : "=f"(r) : "f"(x));
    return r;
}
__device__ __forceinline__ float gelu_f(float x) {
    float x3 = x*x*x;
    return 0.5f * x * (1.0f + tanh_hw(0.79788456080286536f * (x + 0.044715f*x3)));
}

// ---------------- weight transpose -> fp16 (64x64 tiles) ----------------
__global__ __launch_bounds__(256)
void transpose_half(const float* __restrict__ W, __half* __restrict__ Wt,
                    int K, int N, int rowOff, int ldOut) {
    __shared__ float t[64][65];
    int k0 = blockIdx.y * 64, n0 = blockIdx.x * 64;
    int tx = threadIdx.x;
#pragma unroll
    for (int i = 0; i < 4; i++) {
        int idx = i*256 + tx;
        int r = idx >> 4, c4 = (idx & 15)*4;
        float4 v = *(const float4*)(W + (size_t)(k0 + r)*N + n0 + c4);
        t[r][c4] = v.x; t[r][c4+1] = v.y; t[r][c4+2] = v.z; t[r][c4+3] = v.w;
    }
    __syncthreads();
#pragma unroll
    for (int i = 0; i < 2; i++) {
        int idx = i*256 + tx;
        int r = idx >> 3, c8 = (idx & 7)*8;
        __half h[8];
#pragma unroll
        for (int u = 0; u < 8; u++) h[u] = __float2half(t[c8 + u][r]);
        *(uint4*)(Wt + (size_t)(rowOff + n0 + r)*ldOut + k0 + c8) = *(uint4*)h;
    }
}

// ---------------- LayerNorm (T in -> fp16 out) ----------------
template<typename T>
__global__ __launch_bounds__(256)
void ln_kernel(const T* __restrict__ x, const float* __restrict__ sc,
               const float* __restrict__ sh, __half* __restrict__ out) {
    int row = blockIdx.x;
    const T* xr = x + (size_t)row * DD;
    float v[8];
    float s = 0.f, sq = 0.f;
#pragma unroll
    for (int i = 0; i < 8; i++) {
        v[i] = (float)xr[threadIdx.x + i*256];
        s += v[i]; sq += v[i]*v[i];
    }
    __shared__ float rs[8], rq[8];
    __shared__ float s_mean, s_rstd;
#pragma unroll
    for (int o = 16; o > 0; o >>= 1) {
        s  += __shfl_down_sync(0xFFFFFFFFu, s,  o);
        sq += __shfl_down_sync(0xFFFFFFFFu, sq, o);
    }
    int w = threadIdx.x >> 5;
    if ((threadIdx.x & 31) == 0) { rs[w] = s; rq[w] = sq; }
    __syncthreads();
    if (threadIdx.x == 0) {
        float ts = 0.f, tq = 0.f;
#pragma unroll
        for (int i = 0; i < 8; i++) { ts += rs[i]; tq += rq[i]; }
        float mean = ts * (1.0f/DD);
        s_mean = mean;
        s_rstd = rsqrtf(tq * (1.0f/DD) - mean*mean + EPSV);
    }
    __syncthreads();
    float mean = s_mean, rstd = s_rstd;
    __half* orow = out + (size_t)row * DD;
#pragma unroll
    for (int i = 0; i < 8; i++) {
        int d = threadIdx.x + i*256;
        orow[d] = __float2half(sc[d]*(v[i]-mean)*rstd + sh[d]);
    }
}

// ---------------- FP16 GEMM: C = A[M,K] @ Wt[N,K]^T (group-M swizzled raster) ----------------
#define KSTEP   64
#define ROWH    72
#define T_BYTES (128*ROWH*2)
#define STG_B   (2*T_BYTES)
#define G_SMEM  (3*STG_B)
#define GRP_M   8

// EPI 0: Ch=acc  EPI 1: Ch=half(acc+bias+Rf)  EPI 2: Ch=half(gelu(acc+bias))  EPI 3: Cf=acc+bias+Rh
template<int EPI>
__global__ __launch_bounds__(256, 2)
void mma_gemm(const __half* __restrict__ A, const __half* __restrict__ Bt,
              const float* __restrict__ bias, const float* __restrict__ Rf,
              const __half* __restrict__ Rh,
              float* __restrict__ Cf, __half* __restrict__ Ch, int N, int K) {
    extern __shared__ char dsm[];
    const int tid = threadIdx.x;
    const int lane = tid & 31;
    const int wid = tid >> 5;
    const int warpM = wid & 1;
    const int warpN = wid >> 1;

    const int nBlkN = gridDim.x, nBlkM = gridDim.y;
    int bid = blockIdx.y * nBlkN + blockIdx.x;
    int perGrp = GRP_M * nBlkN;
    int grp = bid / perGrp;
    int rem = bid - grp * perGrp;
    int gsz = nBlkM - grp*GRP_M; if (gsz > GRP_M) gsz = GRP_M;
    const int m0 = (grp*GRP_M + rem % gsz) * 128;
    const int n0 = (rem / gsz) * 128;

    const uint32_t sb = smem_u32(dsm);

    float acc[4][4][4];
#pragma unroll
    for (int i = 0; i < 4; i++)
#pragma unroll
        for (int j = 0; j < 4; j++)
#pragma unroll
            for (int u = 0; u < 4; u++) acc[i][j][u] = 0.f;

    const int NT = K / KSTEP;

    auto load_stage = [&](int s, int kk) {
        uint32_t ab = sb + s*STG_B;
        uint32_t bb = ab + T_BYTES;
#pragma unroll
        for (int i = 0; i < 4; i++) {
            int idx = i*256 + tid;
            int r = idx >> 3, c = idx & 7;
            cp_async16(ab + (r*ROWH + c*8)*2, A  + (size_t)(m0 + r)*K + kk + c*8);
            cp_async16(bb + (r*ROWH + c*8)*2, Bt + (size_t)(n0 + r)*K + kk + c*8);
        }
    };

    load_stage(0, 0); cp_commit();
    load_stage(1, KSTEP); cp_commit();

    const int j  = lane >> 3;
    const int rr = lane & 7;
    const uint32_t offA = ((warpM*64 + ((j&1)<<3) + rr) * ROWH + (j>>1)*8) * 2;
    const uint32_t offB = ((warpN*32 + (j>>1)*8  + rr) * ROWH + (j&1)*8) * 2;

    for (int t = 0; t < NT; t++) {
        cp_wait1();
        __syncthreads();
        if (t + 2 < NT) { load_stage((t+2)%3, (t+2)*KSTEP); cp_commit(); }

        int s = t % 3;
        uint32_t abase = sb + s*STG_B + offA;
        uint32_t bbase = sb + s*STG_B + T_BYTES + offB;
#pragma unroll
        for (int k16 = 0; k16 < 4; k16++) {
            uint32_t ka = abase + k16*32;
            uint32_t kb = bbase + k16*32;
            uint32_t afr[4][4];
#pragma unroll
            for (int mt = 0; mt < 4; mt++)
                ldmx4(afr[mt], ka + mt*(16*ROWH*2));
            uint32_t bfr[4][2];
            ldmx4(&bfr[0][0], kb);
            ldmx4(&bfr[2][0], kb + 16*ROWH*2);
#pragma unroll
            for (int mt = 0; mt < 4; mt++)
#pragma unroll
                for (int nt = 0; nt < 4; nt++)
                    mma_f16(acc[mt][nt], afr[mt], bfr[nt]);
        }
    }

#pragma unroll
    for (int mt = 0; mt < 4; mt++) {
#pragma unroll
        for (int half_ = 0; half_ < 2; half_++) {
            int m = m0 + warpM*64 + mt*16 + (lane >> 2) + half_*8;
#pragma unroll
            for (int nt = 0; nt < 4; nt++) {
                int n = n0 + warpN*32 + nt*8 + 2*(lane & 3);
                float v0 = acc[mt][nt][half_*2 + 0];
                float v1 = acc[mt][nt][half_*2 + 1];
                if (EPI == 0) {
                    *(__half2*)(Ch + (size_t)m*N + n) = __floats2half2_rn(v0, v1);
                } else if (EPI == 1) {
                    const float2 bb = *(const float2*)(bias + n);
                    const float2 rv = *(const float2*)(Rf + (size_t)m*N + n);
                    *(__half2*)(Ch + (size_t)m*N + n) =
                        __floats2half2_rn(v0 + bb.x + rv.x, v1 + bb.y + rv.y);
                } else if (EPI == 2) {
                    const float2 bb = *(const float2*)(bias + n);
                    *(__half2*)(Ch + (size_t)m*N + n) =
                        __floats2half2_rn(gelu_f(v0 + bb.x), gelu_f(v1 + bb.y));
                } else {
                    const float2 bb = *(const float2*)(bias + n);
                    __half2 rv = *(const __half2*)(Rh + (size_t)m*N + n);
                    float2 rf = __half22float2(rv);
                    float2 o; o.x = v0 + bb.x + rf.x; o.y = v1 + bb.y + rf.y;
                    *(float2*)(Cf + (size_t)m*N + n) = o;
                }
            }
        }
    }
}

// ---------------- causal flash attention (fp16, KV tile 128, ex2 softmax) ----------------
#define KVROWH 136
#define KV_TILE (128*KVROWH*2)
#define KV_STG  (2*KV_TILE)
#define Q_BYTES (128*KVROWH*2)
#define ATT_SMEM (Q_BYTES + 2*KV_STG)

__global__ __launch_bounds__(256, 1)
void attn_mma(const __half* __restrict__ Q, const __half* __restrict__ Kg,
              const __half* __restrict__ V, __half* __restrict__ O, int ld) {
    extern __shared__ __half hsm[];
    __half* Qs = hsm;
    const uint32_t sb = smem_u32(hsm);

    const int tid = threadIdx.x;
    const int lane = tid & 31;
    const int w = tid >> 5;
    const int r0 = lane >> 2;
    const int c0 = lane & 3;
    const int j  = lane >> 3;
    const int rr = lane & 7;
    const int q0 = blockIdx.x * 128;
    const int b = blockIdx.y >> 4;
    const int h = blockIdx.y & 15;
    const float rscale = 0.12751677003257157f;  // 1/sqrt(128)*log2(e)
    size_t ibase = ((size_t)b * SS) * ld + (size_t)h * HD;
    size_t obase = ((size_t)b * SS) * DD + (size_t)h * HD;

#pragma unroll
    for (int i = 0; i < 8; i++) {
        int idx = i*256 + tid;
        int r = idx >> 4, c = (idx & 15)*8;
        *(uint4*)(Qs + r*KVROWH + c) = *(const uint4*)(Q + ibase + (size_t)(q0 + r)*ld + c);
    }

    auto load_kv = [&](int kt) {
        int s = kt & 1;
        int k0 = kt * 128;
        uint32_t kb = sb + Q_BYTES + s*KV_STG;
        uint32_t vb = kb + KV_TILE;
#pragma unroll
        for (int i = 0; i < 8; i++) {
            int idx = i*256 + tid;
            int r = idx >> 4, c = (idx & 15)*8;
            cp_async16(kb + (r*KVROWH + c)*2, Kg + ibase + (size_t)(k0 + r)*ld + c);
            cp_async16(vb + (r*KVROWH + c)*2, V  + ibase + (size_t)(k0 + r)*ld + c);
        }
    };

    float acc[16][4];
#pragma unroll
    for (int i = 0; i < 16; i++)
#pragma unroll
        for (int u = 0; u < 4; u++) acc[i][u] = 0.f;
    float m0r = -1e30f, m1r = -1e30f, l0r = 0.f, l1r = 0.f;
    const int qi0 = q0 + w*16 + r0;
    const int qi1 = qi0 + 8;

    const uint32_t offQ = ((w*16 + ((j&1)<<3) + rr)*KVROWH + (j>>1)*8)*2;
    const uint32_t offK = (((j>>1)*8 + rr)*KVROWH + (j&1)*8)*2;
    const uint32_t offV = (((j&1)*8 + rr)*KVROWH + (j>>1)*8)*2;

    const int nkt = (q0 >> 7) + 1;
    load_kv(0); cp_commit();

    for (int kt = 0; kt < nkt; kt++) {
        int k0 = kt * 128;
        cp_wait0();
        __syncthreads();
        if (kt + 1 < nkt) { load_kv(kt + 1); cp_commit(); }

        int s = kt & 1;
        const uint32_t sK = sb + Q_BYTES + s*KV_STG;
        const uint32_t sV = sK + KV_TILE;

        float sc[16][4];
#pragma unroll
        for (int nt = 0; nt < 16; nt++)
#pragma unroll
            for (int u = 0; u < 4; u++) sc[nt][u] = 0.f;
#pragma unroll
        for (int kc = 0; kc < 8; kc++) {
            uint32_t a[4];
            ldmx4(a, sb + offQ + kc*32);
#pragma unroll
            for (int g = 0; g < 8; g++) {
                uint32_t bb[4];
                ldmx4(bb, sK + offK + kc*32 + g*(16*KVROWH*2));
                mma_f16(sc[2*g    ], a, bb);
                mma_f16(sc[2*g + 1], a, bb + 2);
            }
        }
#pragma unroll
        for (int nt = 0; nt < 16; nt++)
#pragma unroll
            for (int u = 0; u < 4; u++) sc[nt][u] *= rscale;
        if (k0 + 127 > qi0) {
#pragma unroll
            for (int nt = 0; nt < 16; nt++) {
                int cj = k0 + nt*8 + 2*c0;
                if (cj     > qi0) sc[nt][0] = -1e30f;
                if (cj + 1 > qi0) sc[nt][1] = -1e30f;
                if (cj     > qi1) sc[nt][2] = -1e30f;
                if (cj + 1 > qi1) sc[nt][3] = -1e30f;
            }
        }
        float tm0 = -1e30f, tm1 = -1e30f;
#pragma unroll
        for (int nt = 0; nt < 16; nt++) {
            tm0 = fmaxf(tm0, fmaxf(sc[nt][0], sc[nt][1]));
            tm1 = fmaxf(tm1, fmaxf(sc[nt][2], sc[nt][3]));
        }
        tm0 = fmaxf(tm0, __shfl_xor_sync(0xFFFFFFFFu, tm0, 1));
        tm0 = fmaxf(tm0, __shfl_xor_sync(0xFFFFFFFFu, tm0, 2));
        tm1 = fmaxf(tm1, __shfl_xor_sync(0xFFFFFFFFu, tm1, 1));
        tm1 = fmaxf(tm1, __shfl_xor_sync(0xFFFFFFFFu, tm1, 2));
        float mn0 = fmaxf(m0r, tm0), f0 = ex2f(m0r - mn0);
        float mn1 = fmaxf(m1r, tm1), f1 = ex2f(m1r - mn1);
        float ps0 = 0.f, ps1 = 0.f;
#pragma unroll
        for (int nt = 0; nt < 16; nt++) {
            sc[nt][0] = ex2f(sc[nt][0] - mn0);
            sc[nt][1] = ex2f(sc[nt][1] - mn0);
            sc[nt][2] = ex2f(sc[nt][2] - mn1);
            sc[nt][3] = ex2f(sc[nt][3] - mn1);
            ps0 += sc[nt][0] + sc[nt][1];
            ps1 += sc[nt][2] + sc[nt][3];
        }
        ps0 += __shfl_xor_sync(0xFFFFFFFFu, ps0, 1);
        ps0 += __shfl_xor_sync(0xFFFFFFFFu, ps0, 2);
        ps1 += __shfl_xor_sync(0xFFFFFFFFu, ps1, 1);
        ps1 += __shfl_xor_sync(0xFFFFFFFFu, ps1, 2);
        l0r = l0r*f0 + ps0; m0r = mn0;
        l1r = l1r*f1 + ps1; m1r = mn1;
#pragma unroll
        for (int nt = 0; nt < 16; nt++) {
            acc[nt][0] *= f0; acc[nt][1] *= f0;
            acc[nt][2] *= f1; acc[nt][3] *= f1;
        }
#pragma unroll
        for (int g = 0; g < 8; g++) {
            uint32_t a[4];
            a[0] = pack_h2(sc[2*g  ][0], sc[2*g  ][1]);
            a[1] = pack_h2(sc[2*g  ][2], sc[2*g  ][3]);
            a[2] = pack_h2(sc[2*g+1][0], sc[2*g+1][1]);
            a[3] = pack_h2(sc[2*g+1][2], sc[2*g+1][3]);
#pragma unroll
            for (int g2 = 0; g2 < 8; g2++) {
                uint32_t bb[4];
                ldmx4t(bb, sV + offV + g*(16*KVROWH*2) + g2*32);
                mma_f16(acc[2*g2    ], a, bb);
                mma_f16(acc[2*g2 + 1], a, bb + 2);
            }
        }
    }

    float inv0 = 1.0f / l0r, inv1 = 1.0f / l1r;
#pragma unroll
    for (int nt = 0; nt < 16; nt++) {
        int n = nt*8 + 2*c0;
        *(__half2*)(O + obase + (size_t)qi0*DD + n) = __floats2half2_rn(acc[nt][0]*inv0, acc[nt][1]*inv0);
        *(__half2*)(O + obase + (size_t)qi1*DD + n) = __floats2half2_rn(acc[nt][2]*inv1, acc[nt][3]*inv1);
    }
}

// ---------------- launch ----------------
extern "C" void kernel_launch(void* const* d_in, const int* in_sizes, int n_in,
                              void* d_out, int out_size) {
    const float* x    = (const float*)d_in[0];
    const float* Wq   = (const float*)d_in[1];
    const float* Wk   = (const float*)d_in[2];
    const float* Wv   = (const float*)d_in[3];
    const float* Wo   = (const float*)d_in[4];
    const float* bo   = (const float*)d_in[5];
    const float* ln1s = (const float*)d_in[6];
    const float* ln1b = (const float*)d_in[7];
    const float* ln2s = (const float*)d_in[8];
    const float* ln2b = (const float*)d_in[9];
    const float* W1   = (const float*)d_in[10];
    const float* b1   = (const float*)d_in[11];
    const float* W2   = (const float*)d_in[12];
    const float* b2   = (const float*)d_in[13];
    float* out = (float*)d_out;

    __half *xn, *qkv, *ctx, *h, *ff, *wqkvT, *woT, *w1T, *w2T;
    cudaGetSymbolAddress((void**)&xn,    g_xn);
    cudaGetSymbolAddress((void**)&qkv,   g_qkv);
    cudaGetSymbolAddress((void**)&ctx,   g_ctx);
    cudaGetSymbolAddress((void**)&h,     g_h);
    cudaGetSymbolAddress((void**)&ff,    g_ff);
    cudaGetSymbolAddress((void**)&wqkvT, g_wqkvT);
    cudaGetSymbolAddress((void**)&woT,   g_woT);
    cudaGetSymbolAddress((void**)&w1T,   g_w1T);
    cudaGetSymbolAddress((void**)&w2T,   g_w2T);

    cudaFuncSetAttribute(attn_mma, cudaFuncAttributeMaxDynamicSharedMemorySize, ATT_SMEM);
    cudaFuncSetAttribute(mma_gemm<0>, cudaFuncAttributeMaxDynamicSharedMemorySize, G_SMEM);
    cudaFuncSetAttribute(mma_gemm<1>, cudaFuncAttributeMaxDynamicSharedMemorySize, G_SMEM);
    cudaFuncSetAttribute(mma_gemm<2>, cudaFuncAttributeMaxDynamicSharedMemorySize, G_SMEM);
    cudaFuncSetAttribute(mma_gemm<3>, cudaFuncAttributeMaxDynamicSharedMemorySize, G_SMEM);

    transpose_half<<<dim3(DD/64,  DD/64), 256>>>(Wq, wqkvT, DD, DD, 0,    DD);
    transpose_half<<<dim3(DD/64,  DD/64), 256>>>(Wk, wqkvT, DD, DD, 2048, DD);
    transpose_half<<<dim3(DD/64,  DD/64), 256>>>(Wv, wqkvT, DD, DD, 4096, DD);
    transpose_half<<<dim3(DD/64,  DD/64), 256>>>(Wo, woT, DD, DD, 0, DD);
    transpose_half<<<dim3(DFF/64, DD/64), 256>>>(W1, w1T, DD, DFF, 0, DD);
    transpose_half<<<dim3(DD/64, DFF/64), 256>>>(W2, w2T, DFF, DD, 0, DFF);

    ln_kernel<float><<<MROW, 256>>>(x, ln1s, ln1b, xn);
    mma_gemm<0><<<dim3(QS/128, MROW/128), 256, G_SMEM>>>(
        xn, wqkvT, nullptr, nullptr, nullptr, nullptr, qkv, QS, DD);
    attn_mma<<<dim3(SS/128, BB*HH), 256, ATT_SMEM>>>(qkv, qkv + 2048, qkv + 4096, ctx, QS);
    mma_gemm<1><<<dim3(DD/128, MROW/128), 256, G_SMEM>>>(
        ctx, woT, bo, x, nullptr, nullptr, h, DD, DD);
    ln_kernel<__half><<<MROW, 256>>>(h, ln2s, ln2b, xn);
    mma_gemm<2><<<dim3(DFF/128, MROW/128), 256, G_SMEM>>>(
        xn, w1T, b1, nullptr, nullptr, nullptr, ff, DFF, DD);
    mma_gemm<3><<<dim3(DD/128, MROW/128), 256, G_SMEM>>>(
        ff, w2T, b2, nullptr, h, out, nullptr, DD, DFF);
}